// round 10
// baseline (speedup 1.0000x reference)
#include <cuda_runtime.h>
#include <cuda_bf16.h>
#include <cuda_fp16.h>
#include <cstdint>

#define DIM_M 8192   // B*S
#define DIM_D 2048
#define DIM_H 8192

// ---------------- scratch (static device globals; no allocation) -------------
__device__ __nv_bfloat16 g_xq[(size_t)DIM_M * DIM_D];     // integer-valued quantized activations (bf16)
__device__ float         g_scale[DIM_M];                  // amax/127 per row
__device__ __nv_bfloat16 g_wg[(size_t)DIM_H * DIM_D];     // sign(W_g) bf16
__device__ __nv_bfloat16 g_wu[(size_t)DIM_H * DIM_D];     // sign(W_u) bf16
__device__ __half        g_wd[(size_t)DIM_D * DIM_H];     // sign(W_d) fp16
__device__ __half        g_p[(size_t)DIM_M * DIM_H];      // p * 2^-4, fp16

// ---------------- PTX helpers -------------------------------------------------
__device__ __forceinline__ uint32_t smem_u32(const void* p) {
    uint32_t a;
    asm("{ .reg .u64 t; cvta.to.shared.u64 t, %1; cvt.u32.u64 %0, t; }" : "=r"(a) : "l"(p));
    return a;
}
__device__ __forceinline__ void cp_async16(uint32_t smem, const void* gmem) {
    asm volatile("cp.async.cg.shared.global [%0], [%1], 16;\n" :: "r"(smem), "l"(gmem));
}
__device__ __forceinline__ void cp_commit() { asm volatile("cp.async.commit_group;\n"); }
template<int N> __device__ __forceinline__ void cp_wait_group() {
    asm volatile("cp.async.wait_group %0;\n" :: "n"(N));
}
__device__ __forceinline__ void ldm4(uint32_t* r, uint32_t addr) {
    asm volatile("ldmatrix.sync.aligned.m8n8.x4.shared.b16 {%0,%1,%2,%3}, [%4];"
                 : "=r"(r[0]), "=r"(r[1]), "=r"(r[2]), "=r"(r[3]) : "r"(addr));
}
__device__ __forceinline__ void mma_bf16(float* d, const uint32_t* a, uint32_t b0, uint32_t b1) {
    asm volatile(
        "mma.sync.aligned.m16n8k16.row.col.f32.bf16.bf16.f32 "
        "{%0,%1,%2,%3}, {%4,%5,%6,%7}, {%8,%9}, {%0,%1,%2,%3};\n"
        : "+f"(d[0]), "+f"(d[1]), "+f"(d[2]), "+f"(d[3])
        : "r"(a[0]), "r"(a[1]), "r"(a[2]), "r"(a[3]), "r"(b0), "r"(b1));
}
__device__ __forceinline__ void mma_f16(float* d, const uint32_t* a, uint32_t b0, uint32_t b1) {
    asm volatile(
        "mma.sync.aligned.m16n8k16.row.col.f32.f16.f16.f32 "
        "{%0,%1,%2,%3}, {%4,%5,%6,%7}, {%8,%9}, {%0,%1,%2,%3};\n"
        : "+f"(d[0]), "+f"(d[1]), "+f"(d[2]), "+f"(d[3])
        : "r"(a[0]), "r"(a[1]), "r"(a[2]), "r"(a[3]), "r"(b0), "r"(b1));
}

// ---------------- misc math ---------------------------------------------------
__device__ __forceinline__ float siluf(float x) { return x / (1.0f + expf(-x)); }

__device__ __forceinline__ float block_reduce(float v, float* sm, bool ismax) {
    int lane = threadIdx.x & 31, wid = threadIdx.x >> 5;
    #pragma unroll
    for (int o = 16; o; o >>= 1) {
        float t = __shfl_xor_sync(0xffffffffu, v, o);
        v = ismax ? fmaxf(v, t) : v + t;
    }
    if (lane == 0) sm[wid] = v;
    __syncthreads();
    float out = sm[0];
    #pragma unroll
    for (int i = 1; i < 8; i++) out = ismax ? fmaxf(out, sm[i]) : out + sm[i];
    __syncthreads();
    return out;
}

// ---------------- kernel 1: layernorm + activation quant (bf16 ints) ----------
__global__ __launch_bounds__(256) void quant_kernel(const float* __restrict__ x) {
    const int row = blockIdx.x, tid = threadIdx.x;
    const float4* xr = reinterpret_cast<const float4*>(x + (size_t)row * DIM_D);
    float4 a = xr[2 * tid], b = xr[2 * tid + 1];
    float v[8] = {a.x, a.y, a.z, a.w, b.x, b.y, b.z, b.w};

    __shared__ float sred[8];

    float s = 0.f;
    #pragma unroll
    for (int i = 0; i < 8; i++) s += v[i];
    s = block_reduce(s, sred, false);
    float mean = s * (1.0f / DIM_D);

    float q = 0.f;
    #pragma unroll
    for (int i = 0; i < 8; i++) { float d = v[i] - mean; q += d * d; }
    q = block_reduce(q, sred, false);
    float rstd = rsqrtf(q * (1.0f / DIM_D) + 1e-8f);

    float amax = 0.f;
    #pragma unroll
    for (int i = 0; i < 8; i++) amax = fmaxf(amax, fabsf((v[i] - mean) * rstd));
    amax = block_reduce(amax, sred, true);

    float sq = (amax > 0.f) ? (127.0f / amax) : 0.0f;

    uint32_t packed[4];
    #pragma unroll
    for (int i = 0; i < 4; i++) {
        float t0 = rintf((v[2 * i] - mean) * rstd * sq);
        float t1 = rintf((v[2 * i + 1] - mean) * rstd * sq);
        t0 = fminf(fmaxf(t0, -128.f), 127.f);
        t1 = fminf(fmaxf(t1, -128.f), 127.f);
        uint32_t lo = (uint32_t)__bfloat16_as_ushort(__float2bfloat16(t0));
        uint32_t hi = (uint32_t)__bfloat16_as_ushort(__float2bfloat16(t1));
        packed[i] = lo | (hi << 16);
    }
    reinterpret_cast<uint4*>(g_xq + (size_t)row * DIM_D)[tid] =
        make_uint4(packed[0], packed[1], packed[2], packed[3]);

    if (tid == 0) g_scale[row] = amax * (1.0f / 127.0f);
}

// ---------------- kernel 2: fused sign conversion (Wg,Wu -> bf16; Wd -> fp16) --
__global__ __launch_bounds__(256) void sign_fused_kernel(
        const float4* __restrict__ wg, const float4* __restrict__ wu,
        const float4* __restrict__ wd, int n4) {
    int gi = blockIdx.x * 256 + threadIdx.x;
    int which = gi / n4;          // 0: Wg, 1: Wu, 2: Wd
    int i = gi - which * n4;
    if (which < 2) {
        const float4 v = (which == 0) ? wg[i] : wu[i];
        __nv_bfloat16* o = (which == 0) ? g_wg : g_wu;
        float f0 = (v.x > 0.f) ? 1.f : ((v.x < 0.f) ? -1.f : 0.f);
        float f1 = (v.y > 0.f) ? 1.f : ((v.y < 0.f) ? -1.f : 0.f);
        float f2 = (v.z > 0.f) ? 1.f : ((v.z < 0.f) ? -1.f : 0.f);
        float f3 = (v.w > 0.f) ? 1.f : ((v.w < 0.f) ? -1.f : 0.f);
        uint32_t a0 = (uint32_t)__bfloat16_as_ushort(__float2bfloat16(f0));
        uint32_t a1 = (uint32_t)__bfloat16_as_ushort(__float2bfloat16(f1));
        uint32_t a2 = (uint32_t)__bfloat16_as_ushort(__float2bfloat16(f2));
        uint32_t a3 = (uint32_t)__bfloat16_as_ushort(__float2bfloat16(f3));
        uint2 out;
        out.x = a0 | (a1 << 16);
        out.y = a2 | (a3 << 16);
        reinterpret_cast<uint2*>(o)[i] = out;
    } else {
        const float4 v = wd[i];
        float f0 = (v.x > 0.f) ? 1.f : ((v.x < 0.f) ? -1.f : 0.f);
        float f1 = (v.y > 0.f) ? 1.f : ((v.y < 0.f) ? -1.f : 0.f);
        float f2 = (v.z > 0.f) ? 1.f : ((v.z < 0.f) ? -1.f : 0.f);
        float f3 = (v.w > 0.f) ? 1.f : ((v.w < 0.f) ? -1.f : 0.f);
        __half2 h0 = __floats2half2_rn(f0, f1);
        __half2 h1 = __floats2half2_rn(f2, f3);
        uint2 out;
        out.x = *reinterpret_cast<uint32_t*>(&h0);
        out.y = *reinterpret_cast<uint32_t*>(&h1);
        reinterpret_cast<uint2*>(g_wd)[i] = out;
    }
}

extern __shared__ __align__(128) char dsm[];

// =============================================================================
// GEMM1 (bf16): CTA 128M x 64H (g & u), 4 warps (2x2), warp 64M x 32H.
// BK=64, 3-stage, 2 CTAs/SM. Intensity 32 FLOP/B smem.
// smem stage (144B rows): A[128x144] @0, Bg[64x144] @18432, Bu @27648 (36864/st)
// =============================================================================
#define G1_STAGE 36864
#define G1_SMEM  (3 * G1_STAGE)

__global__ __launch_bounds__(128, 2) void gemm1_bf() {
    const int tid = threadIdx.x, warp = tid >> 5, lane = tid & 31;
    const int bn = blockIdx.x, bm = blockIdx.y;
    const int wm = warp >> 1, wn = warp & 1;
    uint32_t sb = smem_u32(dsm);

    const __nv_bfloat16* Ag = g_xq + (size_t)bm * 128 * DIM_D;
    const __nv_bfloat16* Bg = g_wg + (size_t)bn * 64 * DIM_D;
    const __nv_bfloat16* Bu = g_wu + (size_t)bn * 64 * DIM_D;

    float cg[4][4][4], cu[4][4][4];
    #pragma unroll
    for (int i = 0; i < 4; i++)
        #pragma unroll
        for (int j = 0; j < 4; j++)
            #pragma unroll
            for (int e = 0; e < 4; e++) { cg[i][j][e] = 0.f; cu[i][j][e] = 0.f; }

    auto load = [&](int st, int kt) {
        int k0 = kt * 64;
        uint32_t base = sb + st * G1_STAGE;
        #pragma unroll
        for (int it = 0; it < 8; it++) {          // A: 128 rows x 8 segs
            int ch = tid + it * 128;
            int row = ch >> 3, seg = ch & 7;
            cp_async16(base + row * 144 + seg * 16,
                       Ag + (size_t)row * DIM_D + k0 + seg * 8);
        }
        #pragma unroll
        for (int it = 0; it < 4; it++) {          // Bg + Bu: 64 rows x 8 segs each
            int ch = tid + it * 128;
            int row = ch >> 3, seg = ch & 7;
            uint32_t d = row * 144 + seg * 16;
            size_t gofs = (size_t)row * DIM_D + k0 + seg * 8;
            cp_async16(base + 18432 + d, Bg + gofs);
            cp_async16(base + 27648 + d, Bu + gofs);
        }
        cp_commit();
    };

    load(0, 0); load(1, 1);

    const int NCHUNK = DIM_D / 64;  // 32
    const uint32_t lrow = (lane & 15), lseg = (lane >> 4) << 4;

    for (int kt = 0; kt < NCHUNK; kt++) {
        int st = kt % 3;
        cp_wait_group<1>();
        __syncthreads();
        if (kt + 2 < NCHUNK) load((kt + 2) % 3, kt + 2);
        uint32_t base = sb + st * G1_STAGE;
        #pragma unroll
        for (int kk = 0; kk < 4; kk++) {
            uint32_t koff = kk * 32 + lseg;
            uint32_t a[4][4], bg[2][4], bu[2][4];
            #pragma unroll
            for (int i = 0; i < 4; i++)
                ldm4(a[i], base + (wm * 64 + i * 16 + lrow) * 144 + koff);
            #pragma unroll
            for (int j2 = 0; j2 < 2; j2++) {
                uint32_t rb = (wn * 32 + j2 * 16 + lrow) * 144 + koff;
                ldm4(bg[j2], base + 18432 + rb);
                ldm4(bu[j2], base + 27648 + rb);
            }
            #pragma unroll
            for (int j = 0; j < 4; j++) {
                int j2 = j >> 1, hh = j & 1;
                #pragma unroll
                for (int i = 0; i < 4; i++) {
                    mma_bf16(cg[i][j], a[i], bg[j2][hh], bg[j2][2 + hh]);
                    mma_bf16(cu[i][j], a[i], bu[j2][hh], bu[j2][2 + hh]);
                }
            }
        }
    }

    // epilogue: scale, silu, product, *2^-4, fp16 store
    #pragma unroll
    for (int i = 0; i < 4; i++) {
        #pragma unroll
        for (int h = 0; h < 2; h++) {
            int m = bm * 128 + wm * 64 + i * 16 + (lane >> 2) + h * 8;
            float s = g_scale[m];
            size_t orow = (size_t)m * DIM_H;
            #pragma unroll
            for (int j = 0; j < 4; j++) {
                int n = bn * 64 + wn * 32 + j * 8 + (lane & 3) * 2;
                float g0 = cg[i][j][h * 2 + 0] * s;
                float g1 = cg[i][j][h * 2 + 1] * s;
                float u0 = cu[i][j][h * 2 + 0] * s;
                float u1 = cu[i][j][h * 2 + 1] * s;
                float p0 = siluf(g0) * u0 * 0.0625f;
                float p1 = siluf(g1) * u1 * 0.0625f;
                __half2 hp = __floats2half2_rn(p0, p1);
                *reinterpret_cast<uint32_t*>(g_p + orow + n) =
                    *reinterpret_cast<uint32_t*>(&hp);
            }
        }
    }
}

// =============================================================================
// GEMM3 (fp16): out[M,D] = 16 * (p16 @ sign(Wd)^T). CTA 128M x 128N,
// 4 warps (2x2), warp 64M x 64N. BK=64, 3-stage, 2 CTAs/SM.
// smem stage (144B rows): A[128x144] @0, B[128x144] @18432  (36864/stage)
// =============================================================================
#define G3_STAGE 36864
#define G3_SMEM  (3 * G3_STAGE)

__global__ __launch_bounds__(128, 2) void gemm3_f16(float* __restrict__ out) {
    const int tid = threadIdx.x, warp = tid >> 5, lane = tid & 31;
    const int bn = blockIdx.x, bm = blockIdx.y;
    const int wm = warp >> 1, wn = warp & 1;
    uint32_t sb = smem_u32(dsm);

    const __half* Ap = g_p  + (size_t)bm * 128 * DIM_H;
    const __half* Bw = g_wd + (size_t)bn * 128 * DIM_H;

    float c[4][8][4];
    #pragma unroll
    for (int i = 0; i < 4; i++)
        #pragma unroll
        for (int j = 0; j < 8; j++)
            #pragma unroll
            for (int e = 0; e < 4; e++) c[i][j][e] = 0.f;

    auto load = [&](int st, int kt) {
        int k0 = kt * 64;
        uint32_t base = sb + st * G3_STAGE;
        #pragma unroll
        for (int it = 0; it < 8; it++) {          // A: 128 rows
            int ch = tid + it * 128;
            int row = ch >> 3, seg = ch & 7;
            cp_async16(base + row * 144 + seg * 16,
                       Ap + (size_t)row * DIM_H + k0 + seg * 8);
        }
        #pragma unroll
        for (int it = 0; it < 8; it++) {          // B: 128 rows
            int ch = tid + it * 128;
            int row = ch >> 3, seg = ch & 7;
            cp_async16(base + 18432 + row * 144 + seg * 16,
                       Bw + (size_t)row * DIM_H + k0 + seg * 8);
        }
        cp_commit();
    };

    load(0, 0); load(1, 1);

    const int NCHUNK = DIM_H / 64;  // 128
    const uint32_t lrow = (lane & 15), lseg = (lane >> 4) << 4;

    for (int kt = 0; kt < NCHUNK; kt++) {
        int st = kt % 3;
        cp_wait_group<1>();
        __syncthreads();
        if (kt + 2 < NCHUNK) load((kt + 2) % 3, kt + 2);
        uint32_t base = sb + st * G3_STAGE;
        #pragma unroll
        for (int kk = 0; kk < 4; kk++) {
            uint32_t koff = kk * 32 + lseg;
            uint32_t a[4][4], b[4][4];
            #pragma unroll
            for (int i = 0; i < 4; i++)
                ldm4(a[i], base + (wm * 64 + i * 16 + lrow) * 144 + koff);
            #pragma unroll
            for (int j2 = 0; j2 < 4; j2++)
                ldm4(b[j2], base + 18432 + (wn * 64 + j2 * 16 + lrow) * 144 + koff);
            #pragma unroll
            for (int j = 0; j < 8; j++) {
                int j2 = j >> 1, hh = j & 1;
                #pragma unroll
                for (int i = 0; i < 4; i++)
                    mma_f16(c[i][j], a[i], b[j2][hh], b[j2][2 + hh]);
            }
        }
    }

    #pragma unroll
    for (int i = 0; i < 4; i++) {
        #pragma unroll
        for (int h = 0; h < 2; h++) {
            int m = bm * 128 + wm * 64 + i * 16 + (lane >> 2) + h * 8;
            size_t orow = (size_t)m * DIM_D;
            #pragma unroll
            for (int j = 0; j < 8; j++) {
                int n = bn * 128 + wn * 64 + j * 8 + (lane & 3) * 2;
                float2 o = make_float2(c[i][j][h * 2 + 0] * 16.0f,
                                       c[i][j][h * 2 + 1] * 16.0f);
                *reinterpret_cast<float2*>(out + orow + n) = o;
            }
        }
    }
}

// ---------------- launch ------------------------------------------------------
extern "C" void kernel_launch(void* const* d_in, const int* in_sizes, int n_in,
                              void* d_out, int out_size) {
    const float* x  = (const float*)d_in[0];
    const float* Wg = (const float*)d_in[1];
    const float* Wu = (const float*)d_in[2];
    const float* Wd = (const float*)d_in[3];
    float* out = (float*)d_out;

    cudaFuncSetAttribute(gemm1_bf, cudaFuncAttributeMaxDynamicSharedMemorySize, G1_SMEM);
    cudaFuncSetAttribute(gemm3_f16, cudaFuncAttributeMaxDynamicSharedMemorySize, G3_SMEM);

    quant_kernel<<<DIM_M, 256>>>(x);

    const int n4 = DIM_H * DIM_D / 4;  // 4194304
    sign_fused_kernel<<<3 * n4 / 256, 256>>>((const float4*)Wg, (const float4*)Wu,
                                             (const float4*)Wd, n4);

    dim3 g1(DIM_H / 64, DIM_M / 128);    // (128, 64)
    gemm1_bf<<<g1, 128, G1_SMEM>>>();

    dim3 g3(DIM_D / 128, DIM_M / 128);   // (16, 64)
    gemm3_f16<<<g3, 128, G3_SMEM>>>(out);
}

// round 11
// speedup vs baseline: 1.0152x; 1.0152x over previous
#include <cuda_runtime.h>
#include <cuda_bf16.h>
#include <cuda_fp16.h>
#include <cstdint>

#define DIM_M 8192   // B*S
#define DIM_D 2048
#define DIM_H 8192

// ---------------- scratch (static device globals; no allocation) -------------
__device__ __nv_bfloat16 g_xq[(size_t)DIM_M * DIM_D];     // integer-valued quantized activations (bf16)
__device__ float         g_scale[DIM_M];                  // amax/127 per row
__device__ __nv_bfloat16 g_wg[(size_t)DIM_H * DIM_D];     // sign(W_g) bf16
__device__ __nv_bfloat16 g_wu[(size_t)DIM_H * DIM_D];     // sign(W_u) bf16
__device__ __half        g_wd[(size_t)DIM_D * DIM_H];     // sign(W_d) fp16
__device__ __half        g_p[(size_t)DIM_M * DIM_H];      // p * 2^-4, fp16

// ---------------- PTX helpers -------------------------------------------------
__device__ __forceinline__ uint32_t smem_u32(const void* p) {
    uint32_t a;
    asm("{ .reg .u64 t; cvta.to.shared.u64 t, %1; cvt.u32.u64 %0, t; }" : "=r"(a) : "l"(p));
    return a;
}
__device__ __forceinline__ void cp_async16(uint32_t smem, const void* gmem) {
    asm volatile("cp.async.cg.shared.global [%0], [%1], 16;\n" :: "r"(smem), "l"(gmem));
}
__device__ __forceinline__ void cp_commit() { asm volatile("cp.async.commit_group;\n"); }
template<int N> __device__ __forceinline__ void cp_wait_group() {
    asm volatile("cp.async.wait_group %0;\n" :: "n"(N));
}
__device__ __forceinline__ void ldm4(uint32_t* r, uint32_t addr) {
    asm volatile("ldmatrix.sync.aligned.m8n8.x4.shared.b16 {%0,%1,%2,%3}, [%4];"
                 : "=r"(r[0]), "=r"(r[1]), "=r"(r[2]), "=r"(r[3]) : "r"(addr));
}
__device__ __forceinline__ void mma_bf16(float* d, const uint32_t* a, uint32_t b0, uint32_t b1) {
    asm volatile(
        "mma.sync.aligned.m16n8k16.row.col.f32.bf16.bf16.f32 "
        "{%0,%1,%2,%3}, {%4,%5,%6,%7}, {%8,%9}, {%0,%1,%2,%3};\n"
        : "+f"(d[0]), "+f"(d[1]), "+f"(d[2]), "+f"(d[3])
        : "r"(a[0]), "r"(a[1]), "r"(a[2]), "r"(a[3]), "r"(b0), "r"(b1));
}
__device__ __forceinline__ void mma_f16(float* d, const uint32_t* a, uint32_t b0, uint32_t b1) {
    asm volatile(
        "mma.sync.aligned.m16n8k16.row.col.f32.f16.f16.f32 "
        "{%0,%1,%2,%3}, {%4,%5,%6,%7}, {%8,%9}, {%0,%1,%2,%3};\n"
        : "+f"(d[0]), "+f"(d[1]), "+f"(d[2]), "+f"(d[3])
        : "r"(a[0]), "r"(a[1]), "r"(a[2]), "r"(a[3]), "r"(b0), "r"(b1));
}

// ---------------- misc math ---------------------------------------------------
__device__ __forceinline__ float siluf(float x) { return x / (1.0f + expf(-x)); }

__device__ __forceinline__ float block_reduce(float v, float* sm, bool ismax) {
    int lane = threadIdx.x & 31, wid = threadIdx.x >> 5;
    #pragma unroll
    for (int o = 16; o; o >>= 1) {
        float t = __shfl_xor_sync(0xffffffffu, v, o);
        v = ismax ? fmaxf(v, t) : v + t;
    }
    if (lane == 0) sm[wid] = v;
    __syncthreads();
    float out = sm[0];
    #pragma unroll
    for (int i = 1; i < 8; i++) out = ismax ? fmaxf(out, sm[i]) : out + sm[i];
    __syncthreads();
    return out;
}

// ---------------- kernel 1: layernorm + activation quant (bf16 ints) ----------
__global__ __launch_bounds__(256) void quant_kernel(const float* __restrict__ x) {
    const int row = blockIdx.x, tid = threadIdx.x;
    const float4* xr = reinterpret_cast<const float4*>(x + (size_t)row * DIM_D);
    float4 a = xr[2 * tid], b = xr[2 * tid + 1];
    float v[8] = {a.x, a.y, a.z, a.w, b.x, b.y, b.z, b.w};

    __shared__ float sred[8];

    float s = 0.f;
    #pragma unroll
    for (int i = 0; i < 8; i++) s += v[i];
    s = block_reduce(s, sred, false);
    float mean = s * (1.0f / DIM_D);

    float q = 0.f;
    #pragma unroll
    for (int i = 0; i < 8; i++) { float d = v[i] - mean; q += d * d; }
    q = block_reduce(q, sred, false);
    float rstd = rsqrtf(q * (1.0f / DIM_D) + 1e-8f);

    float amax = 0.f;
    #pragma unroll
    for (int i = 0; i < 8; i++) amax = fmaxf(amax, fabsf((v[i] - mean) * rstd));
    amax = block_reduce(amax, sred, true);

    float sq = (amax > 0.f) ? (127.0f / amax) : 0.0f;

    uint32_t packed[4];
    #pragma unroll
    for (int i = 0; i < 4; i++) {
        float t0 = rintf((v[2 * i] - mean) * rstd * sq);
        float t1 = rintf((v[2 * i + 1] - mean) * rstd * sq);
        t0 = fminf(fmaxf(t0, -128.f), 127.f);
        t1 = fminf(fmaxf(t1, -128.f), 127.f);
        uint32_t lo = (uint32_t)__bfloat16_as_ushort(__float2bfloat16(t0));
        uint32_t hi = (uint32_t)__bfloat16_as_ushort(__float2bfloat16(t1));
        packed[i] = lo | (hi << 16);
    }
    reinterpret_cast<uint4*>(g_xq + (size_t)row * DIM_D)[tid] =
        make_uint4(packed[0], packed[1], packed[2], packed[3]);

    if (tid == 0) g_scale[row] = amax * (1.0f / 127.0f);
}

// ---------------- kernel 2: fused sign conversion (Wg,Wu -> bf16; Wd -> fp16) --
__global__ __launch_bounds__(256) void sign_fused_kernel(
        const float4* __restrict__ wg, const float4* __restrict__ wu,
        const float4* __restrict__ wd, int n4) {
    int gi = blockIdx.x * 256 + threadIdx.x;
    int which = gi / n4;          // 0: Wg, 1: Wu, 2: Wd
    int i = gi - which * n4;
    if (which < 2) {
        const float4 v = (which == 0) ? wg[i] : wu[i];
        __nv_bfloat16* o = (which == 0) ? g_wg : g_wu;
        float f0 = (v.x > 0.f) ? 1.f : ((v.x < 0.f) ? -1.f : 0.f);
        float f1 = (v.y > 0.f) ? 1.f : ((v.y < 0.f) ? -1.f : 0.f);
        float f2 = (v.z > 0.f) ? 1.f : ((v.z < 0.f) ? -1.f : 0.f);
        float f3 = (v.w > 0.f) ? 1.f : ((v.w < 0.f) ? -1.f : 0.f);
        uint32_t a0 = (uint32_t)__bfloat16_as_ushort(__float2bfloat16(f0));
        uint32_t a1 = (uint32_t)__bfloat16_as_ushort(__float2bfloat16(f1));
        uint32_t a2 = (uint32_t)__bfloat16_as_ushort(__float2bfloat16(f2));
        uint32_t a3 = (uint32_t)__bfloat16_as_ushort(__float2bfloat16(f3));
        uint2 out;
        out.x = a0 | (a1 << 16);
        out.y = a2 | (a3 << 16);
        reinterpret_cast<uint2*>(o)[i] = out;
    } else {
        const float4 v = wd[i];
        float f0 = (v.x > 0.f) ? 1.f : ((v.x < 0.f) ? -1.f : 0.f);
        float f1 = (v.y > 0.f) ? 1.f : ((v.y < 0.f) ? -1.f : 0.f);
        float f2 = (v.z > 0.f) ? 1.f : ((v.z < 0.f) ? -1.f : 0.f);
        float f3 = (v.w > 0.f) ? 1.f : ((v.w < 0.f) ? -1.f : 0.f);
        __half2 h0 = __floats2half2_rn(f0, f1);
        __half2 h1 = __floats2half2_rn(f2, f3);
        uint2 out;
        out.x = *reinterpret_cast<uint32_t*>(&h0);
        out.y = *reinterpret_cast<uint32_t*>(&h1);
        reinterpret_cast<uint2*>(g_wd)[i] = out;
    }
}

extern __shared__ __align__(128) char dsm[];

// =============================================================================
// GEMM1 (bf16), PERSISTENT: tiles = (bn 0..127) x (bm 0..63), bn fast.
// CTA tile 128M x 64H computing g & u. 256 thr, warp 32x64-equivalent (R8 shape).
// 2-stage pipeline runs continuously across (tile, kt) chunks.
// smem stage (144B rows): A[128x144] @0, Bg[64x144] @18432, Bu @27648 (36864/st)
// =============================================================================
#define G1_STAGE 36864
#define G1_SMEM  (2 * G1_STAGE)
#define G1_TILES (128 * 64)
#define G1_NCHUNK (DIM_D / 64)   // 32

__global__ __launch_bounds__(256, 2) void gemm1_bf(int ncta) {
    const int tid = threadIdx.x, warp = tid >> 5, lane = tid & 31;
    const int wm = warp & 3, wn = warp >> 2;
    uint32_t sb = smem_u32(dsm);

    float cg[2][4][4], cu[2][4][4];
    #pragma unroll
    for (int i = 0; i < 2; i++)
        #pragma unroll
        for (int j = 0; j < 4; j++)
            #pragma unroll
            for (int e = 0; e < 4; e++) { cg[i][j][e] = 0.f; cu[i][j][e] = 0.f; }

    auto load = [&](int st, int t, int kt) {
        int bm = t >> 7, bn = t & 127;
        const __nv_bfloat16* Ag = g_xq + (size_t)bm * 128 * DIM_D;
        const __nv_bfloat16* Bg = g_wg + (size_t)bn * 64 * DIM_D;
        const __nv_bfloat16* Bu = g_wu + (size_t)bn * 64 * DIM_D;
        int k0 = kt * 64;
        uint32_t base = sb + st * G1_STAGE;
        #pragma unroll
        for (int it = 0; it < 4; it++) {
            int ch = tid + it * 256;
            int row = ch >> 3, seg = ch & 7;
            cp_async16(base + row * 144 + seg * 16,
                       Ag + (size_t)row * DIM_D + k0 + seg * 8);
        }
        #pragma unroll
        for (int it = 0; it < 2; it++) {
            int ch = tid + it * 256;
            int row = ch >> 3, seg = ch & 7;
            uint32_t d = row * 144 + seg * 16;
            size_t gofs = (size_t)row * DIM_D + k0 + seg * 8;
            cp_async16(base + 18432 + d, Bg + gofs);
            cp_async16(base + 27648 + d, Bu + gofs);
        }
        cp_commit();
    };

    const uint32_t lrow = (lane & 15), lseg = (lane >> 4) << 4;
    int lt = blockIdx.x, lk = 0;       // load cursor (one chunk ahead)
    load(0, lt, 0);
    int st = 0;

    for (int t = blockIdx.x; t < G1_TILES; t += ncta) {
        for (int kt = 0; kt < G1_NCHUNK; kt++) {
            cp_wait_group<0>();
            __syncthreads();
            // advance load cursor, issue next chunk into the other stage
            if (++lk == G1_NCHUNK) { lk = 0; lt += ncta; }
            if (lt < G1_TILES) load(st ^ 1, lt, lk);
            uint32_t base = sb + st * G1_STAGE;
            #pragma unroll
            for (int kk = 0; kk < 4; kk++) {
                uint32_t koff = kk * 32 + lseg;
                uint32_t a[2][4], bg[2][4], bu[2][4];
                #pragma unroll
                for (int i = 0; i < 2; i++)
                    ldm4(a[i], base + (wm * 32 + i * 16 + lrow) * 144 + koff);
                #pragma unroll
                for (int j2 = 0; j2 < 2; j2++) {
                    uint32_t rb = (wn * 32 + j2 * 16 + lrow) * 144 + koff;
                    ldm4(bg[j2], base + 18432 + rb);
                    ldm4(bu[j2], base + 27648 + rb);
                }
                #pragma unroll
                for (int j = 0; j < 4; j++) {
                    int j2 = j >> 1, hh = j & 1;
                    #pragma unroll
                    for (int i = 0; i < 2; i++) {
                        mma_bf16(cg[i][j], a[i], bg[j2][hh], bg[j2][2 + hh]);
                        mma_bf16(cu[i][j], a[i], bu[j2][hh], bu[j2][2 + hh]);
                    }
                }
            }
            st ^= 1;
        }

        // epilogue for tile t: scale, silu, product, *2^-4, fp16 store; zero accs
        int bm = t >> 7, bn = t & 127;
        #pragma unroll
        for (int i = 0; i < 2; i++) {
            #pragma unroll
            for (int h = 0; h < 2; h++) {
                int m = bm * 128 + wm * 32 + i * 16 + (lane >> 2) + h * 8;
                float s = g_scale[m];
                size_t orow = (size_t)m * DIM_H;
                #pragma unroll
                for (int j = 0; j < 4; j++) {
                    int n = bn * 64 + wn * 32 + j * 8 + (lane & 3) * 2;
                    float g0 = cg[i][j][h * 2 + 0] * s;
                    float g1 = cg[i][j][h * 2 + 1] * s;
                    float u0 = cu[i][j][h * 2 + 0] * s;
                    float u1 = cu[i][j][h * 2 + 1] * s;
                    float p0 = siluf(g0) * u0 * 0.0625f;
                    float p1 = siluf(g1) * u1 * 0.0625f;
                    __half2 hp = __floats2half2_rn(p0, p1);
                    *reinterpret_cast<uint32_t*>(g_p + orow + n) =
                        *reinterpret_cast<uint32_t*>(&hp);
                }
            }
        }
        #pragma unroll
        for (int i = 0; i < 2; i++)
            #pragma unroll
            for (int j = 0; j < 4; j++)
                #pragma unroll
                for (int e = 0; e < 4; e++) { cg[i][j][e] = 0.f; cu[i][j][e] = 0.f; }
    }
}

// =============================================================================
// GEMM3 (fp16), PERSISTENT: tiles = (bn 0..15) x (bm 0..63), bn fast.
// CTA 128M x 128N (two 64-col B halves sharing A fragments). R8 shape.
// smem stage (144B rows): A[128x144] @0, B0[64x144] @18432, B1 @27648 (36864/st)
// =============================================================================
#define G3_STAGE 36864
#define G3_SMEM  (2 * G3_STAGE)
#define G3_TILES (16 * 64)
#define G3_NCHUNK (DIM_H / 64)   // 128

__global__ __launch_bounds__(256, 2) void gemm3_f16(float* __restrict__ out, int ncta) {
    const int tid = threadIdx.x, warp = tid >> 5, lane = tid & 31;
    const int wm = warp & 3, wn = warp >> 2;
    uint32_t sb = smem_u32(dsm);

    float c0[2][4][4], c1[2][4][4];
    #pragma unroll
    for (int i = 0; i < 2; i++)
        #pragma unroll
        for (int j = 0; j < 4; j++)
            #pragma unroll
            for (int e = 0; e < 4; e++) { c0[i][j][e] = 0.f; c1[i][j][e] = 0.f; }

    auto load = [&](int st, int t, int kt) {
        int bm = t >> 4, bn = t & 15;
        const __half* Ap = g_p  + (size_t)bm * 128 * DIM_H;
        const __half* B0 = g_wd + (size_t)bn * 128 * DIM_H;
        const __half* B1 = B0 + (size_t)64 * DIM_H;
        int k0 = kt * 64;
        uint32_t base = sb + st * G3_STAGE;
        #pragma unroll
        for (int it = 0; it < 4; it++) {
            int ch = tid + it * 256;
            int row = ch >> 3, seg = ch & 7;
            cp_async16(base + row * 144 + seg * 16,
                       Ap + (size_t)row * DIM_H + k0 + seg * 8);
        }
        #pragma unroll
        for (int it = 0; it < 2; it++) {
            int ch = tid + it * 256;
            int row = ch >> 3, seg = ch & 7;
            uint32_t d = row * 144 + seg * 16;
            size_t gofs = (size_t)row * DIM_H + k0 + seg * 8;
            cp_async16(base + 18432 + d, B0 + gofs);
            cp_async16(base + 27648 + d, B1 + gofs);
        }
        cp_commit();
    };

    const uint32_t lrow = (lane & 15), lseg = (lane >> 4) << 4;
    int lt = blockIdx.x, lk = 0;
    load(0, lt, 0);
    int st = 0;

    for (int t = blockIdx.x; t < G3_TILES; t += ncta) {
        for (int kt = 0; kt < G3_NCHUNK; kt++) {
            cp_wait_group<0>();
            __syncthreads();
            if (++lk == G3_NCHUNK) { lk = 0; lt += ncta; }
            if (lt < G3_TILES) load(st ^ 1, lt, lk);
            uint32_t base = sb + st * G3_STAGE;
            #pragma unroll
            for (int kk = 0; kk < 4; kk++) {
                uint32_t koff = kk * 32 + lseg;
                uint32_t a[2][4], b0[2][4], b1[2][4];
                #pragma unroll
                for (int i = 0; i < 2; i++)
                    ldm4(a[i], base + (wm * 32 + i * 16 + lrow) * 144 + koff);
                #pragma unroll
                for (int j2 = 0; j2 < 2; j2++) {
                    uint32_t rb = (wn * 32 + j2 * 16 + lrow) * 144 + koff;
                    ldm4(b0[j2], base + 18432 + rb);
                    ldm4(b1[j2], base + 27648 + rb);
                }
                #pragma unroll
                for (int j = 0; j < 4; j++) {
                    int j2 = j >> 1, hh = j & 1;
                    #pragma unroll
                    for (int i = 0; i < 2; i++) {
                        mma_f16(c0[i][j], a[i], b0[j2][hh], b0[j2][2 + hh]);
                        mma_f16(c1[i][j], a[i], b1[j2][hh], b1[j2][2 + hh]);
                    }
                }
            }
            st ^= 1;
        }

        int bm = t >> 4, bn = t & 15;
        #pragma unroll
        for (int i = 0; i < 2; i++) {
            #pragma unroll
            for (int h = 0; h < 2; h++) {
                int m = bm * 128 + wm * 32 + i * 16 + (lane >> 2) + h * 8;
                size_t orow = (size_t)m * DIM_D;
                #pragma unroll
                for (int j = 0; j < 4; j++) {
                    int n = bn * 128 + wn * 32 + j * 8 + (lane & 3) * 2;
                    float2 o0 = make_float2(c0[i][j][h * 2 + 0] * 16.0f,
                                            c0[i][j][h * 2 + 1] * 16.0f);
                    float2 o1 = make_float2(c1[i][j][h * 2 + 0] * 16.0f,
                                            c1[i][j][h * 2 + 1] * 16.0f);
                    *reinterpret_cast<float2*>(out + orow + n) = o0;
                    *reinterpret_cast<float2*>(out + orow + n + 64) = o1;
                }
            }
        }
        #pragma unroll
        for (int i = 0; i < 2; i++)
            #pragma unroll
            for (int j = 0; j < 4; j++)
                #pragma unroll
                for (int e = 0; e < 4; e++) { c0[i][j][e] = 0.f; c1[i][j][e] = 0.f; }
    }
}

// ---------------- launch ------------------------------------------------------
extern "C" void kernel_launch(void* const* d_in, const int* in_sizes, int n_in,
                              void* d_out, int out_size) {
    const float* x  = (const float*)d_in[0];
    const float* Wg = (const float*)d_in[1];
    const float* Wu = (const float*)d_in[2];
    const float* Wd = (const float*)d_in[3];
    float* out = (float*)d_out;

    int nsm = 148;
    cudaDeviceGetAttribute(&nsm, cudaDevAttrMultiProcessorCount, 0);
    int ncta = 2 * nsm;

    cudaFuncSetAttribute(gemm1_bf, cudaFuncAttributeMaxDynamicSharedMemorySize, G1_SMEM);
    cudaFuncSetAttribute(gemm3_f16, cudaFuncAttributeMaxDynamicSharedMemorySize, G3_SMEM);

    quant_kernel<<<DIM_M, 256>>>(x);

    const int n4 = DIM_H * DIM_D / 4;  // 4194304
    sign_fused_kernel<<<3 * n4 / 256, 256>>>((const float4*)Wg, (const float4*)Wu,
                                             (const float4*)Wd, n4);

    gemm1_bf<<<ncta, 256, G1_SMEM>>>(ncta);

    gemm3_f16<<<ncta, 256, G3_SMEM>>>(out, ncta);
}

// round 12
// speedup vs baseline: 1.0548x; 1.0389x over previous
#include <cuda_runtime.h>
#include <cuda_bf16.h>
#include <cuda_fp16.h>
#include <cstdint>

#define DIM_M 8192   // B*S
#define DIM_D 2048
#define DIM_H 8192

// ---------------- scratch (static device globals; no allocation) -------------
__device__ __nv_bfloat16 g_xq[(size_t)DIM_M * DIM_D];     // integer-valued quantized activations (bf16)
__device__ float         g_scale[DIM_M];                  // amax/127 per row
__device__ __nv_bfloat16 g_wg[(size_t)DIM_H * DIM_D];     // sign(W_g) bf16
__device__ __nv_bfloat16 g_wu[(size_t)DIM_H * DIM_D];     // sign(W_u) bf16
__device__ __half        g_wd[(size_t)DIM_D * DIM_H];     // sign(W_d) fp16
__device__ __half        g_p[(size_t)DIM_M * DIM_H];      // p * 2^-4, fp16
__device__ int           g_t1;                            // gemm1 tile queue head
__device__ int           g_t3;                            // gemm3 tile queue head

// ---------------- PTX helpers -------------------------------------------------
__device__ __forceinline__ uint32_t smem_u32(const void* p) {
    uint32_t a;
    asm("{ .reg .u64 t; cvta.to.shared.u64 t, %1; cvt.u32.u64 %0, t; }" : "=r"(a) : "l"(p));
    return a;
}
__device__ __forceinline__ void cp_async16(uint32_t smem, const void* gmem) {
    asm volatile("cp.async.cg.shared.global [%0], [%1], 16;\n" :: "r"(smem), "l"(gmem));
}
__device__ __forceinline__ void cp_commit() { asm volatile("cp.async.commit_group;\n"); }
template<int N> __device__ __forceinline__ void cp_wait_group() {
    asm volatile("cp.async.wait_group %0;\n" :: "n"(N));
}
__device__ __forceinline__ void ldm4(uint32_t* r, uint32_t addr) {
    asm volatile("ldmatrix.sync.aligned.m8n8.x4.shared.b16 {%0,%1,%2,%3}, [%4];"
                 : "=r"(r[0]), "=r"(r[1]), "=r"(r[2]), "=r"(r[3]) : "r"(addr));
}
__device__ __forceinline__ void mma_bf16(float* d, const uint32_t* a, uint32_t b0, uint32_t b1) {
    asm volatile(
        "mma.sync.aligned.m16n8k16.row.col.f32.bf16.bf16.f32 "
        "{%0,%1,%2,%3}, {%4,%5,%6,%7}, {%8,%9}, {%0,%1,%2,%3};\n"
        : "+f"(d[0]), "+f"(d[1]), "+f"(d[2]), "+f"(d[3])
        : "r"(a[0]), "r"(a[1]), "r"(a[2]), "r"(a[3]), "r"(b0), "r"(b1));
}
__device__ __forceinline__ void mma_f16(float* d, const uint32_t* a, uint32_t b0, uint32_t b1) {
    asm volatile(
        "mma.sync.aligned.m16n8k16.row.col.f32.f16.f16.f32 "
        "{%0,%1,%2,%3}, {%4,%5,%6,%7}, {%8,%9}, {%0,%1,%2,%3};\n"
        : "+f"(d[0]), "+f"(d[1]), "+f"(d[2]), "+f"(d[3])
        : "r"(a[0]), "r"(a[1]), "r"(a[2]), "r"(a[3]), "r"(b0), "r"(b1));
}

// ---------------- misc math ---------------------------------------------------
__device__ __forceinline__ float siluf(float x) { return x / (1.0f + expf(-x)); }

__device__ __forceinline__ float block_reduce(float v, float* sm, bool ismax) {
    int lane = threadIdx.x & 31, wid = threadIdx.x >> 5;
    #pragma unroll
    for (int o = 16; o; o >>= 1) {
        float t = __shfl_xor_sync(0xffffffffu, v, o);
        v = ismax ? fmaxf(v, t) : v + t;
    }
    if (lane == 0) sm[wid] = v;
    __syncthreads();
    float out = sm[0];
    #pragma unroll
    for (int i = 1; i < 8; i++) out = ismax ? fmaxf(out, sm[i]) : out + sm[i];
    __syncthreads();
    return out;
}

// ---------------- kernel 1: layernorm + activation quant (bf16 ints) ----------
__global__ __launch_bounds__(256) void quant_kernel(const float* __restrict__ x) {
    const int row = blockIdx.x, tid = threadIdx.x;
    if (row == 0 && tid == 0) { g_t1 = 0; g_t3 = 0; }   // reset tile queues per launch
    const float4* xr = reinterpret_cast<const float4*>(x + (size_t)row * DIM_D);
    float4 a = xr[2 * tid], b = xr[2 * tid + 1];
    float v[8] = {a.x, a.y, a.z, a.w, b.x, b.y, b.z, b.w};

    __shared__ float sred[8];

    float s = 0.f;
    #pragma unroll
    for (int i = 0; i < 8; i++) s += v[i];
    s = block_reduce(s, sred, false);
    float mean = s * (1.0f / DIM_D);

    float q = 0.f;
    #pragma unroll
    for (int i = 0; i < 8; i++) { float d = v[i] - mean; q += d * d; }
    q = block_reduce(q, sred, false);
    float rstd = rsqrtf(q * (1.0f / DIM_D) + 1e-8f);

    float amax = 0.f;
    #pragma unroll
    for (int i = 0; i < 8; i++) amax = fmaxf(amax, fabsf((v[i] - mean) * rstd));
    amax = block_reduce(amax, sred, true);

    float sq = (amax > 0.f) ? (127.0f / amax) : 0.0f;

    uint32_t packed[4];
    #pragma unroll
    for (int i = 0; i < 4; i++) {
        float t0 = rintf((v[2 * i] - mean) * rstd * sq);
        float t1 = rintf((v[2 * i + 1] - mean) * rstd * sq);
        t0 = fminf(fmaxf(t0, -128.f), 127.f);
        t1 = fminf(fmaxf(t1, -128.f), 127.f);
        uint32_t lo = (uint32_t)__bfloat16_as_ushort(__float2bfloat16(t0));
        uint32_t hi = (uint32_t)__bfloat16_as_ushort(__float2bfloat16(t1));
        packed[i] = lo | (hi << 16);
    }
    reinterpret_cast<uint4*>(g_xq + (size_t)row * DIM_D)[tid] =
        make_uint4(packed[0], packed[1], packed[2], packed[3]);

    if (tid == 0) g_scale[row] = amax * (1.0f / 127.0f);
}

// ---------------- kernel 2: fused sign conversion (Wg,Wu -> bf16; Wd -> fp16) --
__global__ __launch_bounds__(256) void sign_fused_kernel(
        const float4* __restrict__ wg, const float4* __restrict__ wu,
        const float4* __restrict__ wd, int n4) {
    int gi = blockIdx.x * 256 + threadIdx.x;
    int which = gi / n4;          // 0: Wg, 1: Wu, 2: Wd
    int i = gi - which * n4;
    if (which < 2) {
        const float4 v = (which == 0) ? wg[i] : wu[i];
        __nv_bfloat16* o = (which == 0) ? g_wg : g_wu;
        float f0 = (v.x > 0.f) ? 1.f : ((v.x < 0.f) ? -1.f : 0.f);
        float f1 = (v.y > 0.f) ? 1.f : ((v.y < 0.f) ? -1.f : 0.f);
        float f2 = (v.z > 0.f) ? 1.f : ((v.z < 0.f) ? -1.f : 0.f);
        float f3 = (v.w > 0.f) ? 1.f : ((v.w < 0.f) ? -1.f : 0.f);
        uint32_t a0 = (uint32_t)__bfloat16_as_ushort(__float2bfloat16(f0));
        uint32_t a1 = (uint32_t)__bfloat16_as_ushort(__float2bfloat16(f1));
        uint32_t a2 = (uint32_t)__bfloat16_as_ushort(__float2bfloat16(f2));
        uint32_t a3 = (uint32_t)__bfloat16_as_ushort(__float2bfloat16(f3));
        uint2 out;
        out.x = a0 | (a1 << 16);
        out.y = a2 | (a3 << 16);
        reinterpret_cast<uint2*>(o)[i] = out;
    } else {
        const float4 v = wd[i];
        float f0 = (v.x > 0.f) ? 1.f : ((v.x < 0.f) ? -1.f : 0.f);
        float f1 = (v.y > 0.f) ? 1.f : ((v.y < 0.f) ? -1.f : 0.f);
        float f2 = (v.z > 0.f) ? 1.f : ((v.z < 0.f) ? -1.f : 0.f);
        float f3 = (v.w > 0.f) ? 1.f : ((v.w < 0.f) ? -1.f : 0.f);
        __half2 h0 = __floats2half2_rn(f0, f1);
        __half2 h1 = __floats2half2_rn(f2, f3);
        uint2 out;
        out.x = *reinterpret_cast<uint32_t*>(&h0);
        out.y = *reinterpret_cast<uint32_t*>(&h1);
        reinterpret_cast<uint2*>(g_wd)[i] = out;
    }
}

extern __shared__ __align__(128) char dsm[];

// =============================================================================
// GEMM1 (bf16), PERSISTENT + DYNAMIC QUEUE. Tile: CTA 128M x 64H (g & u),
// 256 thr, warp 32Mx64-equiv (R8 shape). 2-stage, 2 CTAs/SM.
// smem stage (144B rows): A[128x144] @0, Bg[64x144] @18432, Bu @27648 (36864/st)
// =============================================================================
#define G1_STAGE 36864
#define G1_SMEM  (2 * G1_STAGE + 128)
#define G1_TILES (128 * 64)
#define G1_NCHUNK (DIM_D / 64)   // 32

__global__ __launch_bounds__(256, 2) void gemm1_bf() {
    const int tid = threadIdx.x, warp = tid >> 5, lane = tid & 31;
    const int wm = warp & 3, wn = warp >> 2;
    uint32_t sb = smem_u32(dsm);
    int* s_t = reinterpret_cast<int*>(dsm + 2 * G1_STAGE);

    const uint32_t lrow = (lane & 15), lseg = (lane >> 4) << 4;

    while (true) {
        if (tid == 0) *s_t = atomicAdd(&g_t1, 1);
        __syncthreads();
        int t = *s_t;
        if (t >= G1_TILES) break;
        int bm = t >> 7, bn = t & 127;

        const __nv_bfloat16* Ag = g_xq + (size_t)bm * 128 * DIM_D;
        const __nv_bfloat16* Bg = g_wg + (size_t)bn * 64 * DIM_D;
        const __nv_bfloat16* Bu = g_wu + (size_t)bn * 64 * DIM_D;

        float cg[2][4][4], cu[2][4][4];
        #pragma unroll
        for (int i = 0; i < 2; i++)
            #pragma unroll
            for (int j = 0; j < 4; j++)
                #pragma unroll
                for (int e = 0; e < 4; e++) { cg[i][j][e] = 0.f; cu[i][j][e] = 0.f; }

        auto load = [&](int st, int kt) {
            int k0 = kt * 64;
            uint32_t base = sb + st * G1_STAGE;
            #pragma unroll
            for (int it = 0; it < 4; it++) {
                int ch = tid + it * 256;
                int row = ch >> 3, seg = ch & 7;
                cp_async16(base + row * 144 + seg * 16,
                           Ag + (size_t)row * DIM_D + k0 + seg * 8);
            }
            #pragma unroll
            for (int it = 0; it < 2; it++) {
                int ch = tid + it * 256;
                int row = ch >> 3, seg = ch & 7;
                uint32_t d = row * 144 + seg * 16;
                size_t gofs = (size_t)row * DIM_D + k0 + seg * 8;
                cp_async16(base + 18432 + d, Bg + gofs);
                cp_async16(base + 27648 + d, Bu + gofs);
            }
            cp_commit();
        };

        load(0, 0);
        for (int kt = 0; kt < G1_NCHUNK; kt++) {
            int st = kt & 1;
            cp_wait_group<0>();
            __syncthreads();
            if (kt + 1 < G1_NCHUNK) load(st ^ 1, kt + 1);
            uint32_t base = sb + st * G1_STAGE;
            #pragma unroll
            for (int kk = 0; kk < 4; kk++) {
                uint32_t koff = kk * 32 + lseg;
                uint32_t a[2][4], bg[2][4], bu[2][4];
                #pragma unroll
                for (int i = 0; i < 2; i++)
                    ldm4(a[i], base + (wm * 32 + i * 16 + lrow) * 144 + koff);
                #pragma unroll
                for (int j2 = 0; j2 < 2; j2++) {
                    uint32_t rb = (wn * 32 + j2 * 16 + lrow) * 144 + koff;
                    ldm4(bg[j2], base + 18432 + rb);
                    ldm4(bu[j2], base + 27648 + rb);
                }
                #pragma unroll
                for (int j = 0; j < 4; j++) {
                    int j2 = j >> 1, hh = j & 1;
                    #pragma unroll
                    for (int i = 0; i < 2; i++) {
                        mma_bf16(cg[i][j], a[i], bg[j2][hh], bg[j2][2 + hh]);
                        mma_bf16(cu[i][j], a[i], bu[j2][hh], bu[j2][2 + hh]);
                    }
                }
            }
        }

        // epilogue: scale, silu, product, *2^-4, fp16 store
        #pragma unroll
        for (int i = 0; i < 2; i++) {
            #pragma unroll
            for (int h = 0; h < 2; h++) {
                int m = bm * 128 + wm * 32 + i * 16 + (lane >> 2) + h * 8;
                float s = g_scale[m];
                size_t orow = (size_t)m * DIM_H;
                #pragma unroll
                for (int j = 0; j < 4; j++) {
                    int n = bn * 64 + wn * 32 + j * 8 + (lane & 3) * 2;
                    float g0 = cg[i][j][h * 2 + 0] * s;
                    float g1 = cg[i][j][h * 2 + 1] * s;
                    float u0 = cu[i][j][h * 2 + 0] * s;
                    float u1 = cu[i][j][h * 2 + 1] * s;
                    float p0 = siluf(g0) * u0 * 0.0625f;
                    float p1 = siluf(g1) * u1 * 0.0625f;
                    __half2 hp = __floats2half2_rn(p0, p1);
                    *reinterpret_cast<uint32_t*>(g_p + orow + n) =
                        *reinterpret_cast<uint32_t*>(&hp);
                }
            }
        }
    }
}

// =============================================================================
// GEMM3 (fp16), PERSISTENT + DYNAMIC QUEUE. Tile: CTA 128M x 128N (two 64-col
// B halves sharing A fragments). 256 thr, 2-stage, 2 CTAs/SM. R8 shape.
// smem stage (144B rows): A[128x144] @0, B0[64x144] @18432, B1 @27648 (36864/st)
// =============================================================================
#define G3_STAGE 36864
#define G3_SMEM  (2 * G3_STAGE + 128)
#define G3_TILES (16 * 64)
#define G3_NCHUNK (DIM_H / 64)   // 128

__global__ __launch_bounds__(256, 2) void gemm3_f16(float* __restrict__ out) {
    const int tid = threadIdx.x, warp = tid >> 5, lane = tid & 31;
    const int wm = warp & 3, wn = warp >> 2;
    uint32_t sb = smem_u32(dsm);
    int* s_t = reinterpret_cast<int*>(dsm + 2 * G3_STAGE);

    const uint32_t lrow = (lane & 15), lseg = (lane >> 4) << 4;

    while (true) {
        if (tid == 0) *s_t = atomicAdd(&g_t3, 1);
        __syncthreads();
        int t = *s_t;
        if (t >= G3_TILES) break;
        int bm = t >> 4, bn = t & 15;

        const __half* Ap = g_p  + (size_t)bm * 128 * DIM_H;
        const __half* B0 = g_wd + (size_t)bn * 128 * DIM_H;
        const __half* B1 = B0 + (size_t)64 * DIM_H;

        float c0[2][4][4], c1[2][4][4];
        #pragma unroll
        for (int i = 0; i < 2; i++)
            #pragma unroll
            for (int j = 0; j < 4; j++)
                #pragma unroll
                for (int e = 0; e < 4; e++) { c0[i][j][e] = 0.f; c1[i][j][e] = 0.f; }

        auto load = [&](int st, int kt) {
            int k0 = kt * 64;
            uint32_t base = sb + st * G3_STAGE;
            #pragma unroll
            for (int it = 0; it < 4; it++) {
                int ch = tid + it * 256;
                int row = ch >> 3, seg = ch & 7;
                cp_async16(base + row * 144 + seg * 16,
                           Ap + (size_t)row * DIM_H + k0 + seg * 8);
            }
            #pragma unroll
            for (int it = 0; it < 2; it++) {
                int ch = tid + it * 256;
                int row = ch >> 3, seg = ch & 7;
                uint32_t d = row * 144 + seg * 16;
                size_t gofs = (size_t)row * DIM_H + k0 + seg * 8;
                cp_async16(base + 18432 + d, B0 + gofs);
                cp_async16(base + 27648 + d, B1 + gofs);
            }
            cp_commit();
        };

        load(0, 0);
        for (int kt = 0; kt < G3_NCHUNK; kt++) {
            int st = kt & 1;
            cp_wait_group<0>();
            __syncthreads();
            if (kt + 1 < G3_NCHUNK) load(st ^ 1, kt + 1);
            uint32_t base = sb + st * G3_STAGE;
            #pragma unroll
            for (int kk = 0; kk < 4; kk++) {
                uint32_t koff = kk * 32 + lseg;
                uint32_t a[2][4], b0[2][4], b1[2][4];
                #pragma unroll
                for (int i = 0; i < 2; i++)
                    ldm4(a[i], base + (wm * 32 + i * 16 + lrow) * 144 + koff);
                #pragma unroll
                for (int j2 = 0; j2 < 2; j2++) {
                    uint32_t rb = (wn * 32 + j2 * 16 + lrow) * 144 + koff;
                    ldm4(b0[j2], base + 18432 + rb);
                    ldm4(b1[j2], base + 27648 + rb);
                }
                #pragma unroll
                for (int j = 0; j < 4; j++) {
                    int j2 = j >> 1, hh = j & 1;
                    #pragma unroll
                    for (int i = 0; i < 2; i++) {
                        mma_f16(c0[i][j], a[i], b0[j2][hh], b0[j2][2 + hh]);
                        mma_f16(c1[i][j], a[i], b1[j2][hh], b1[j2][2 + hh]);
                    }
                }
            }
        }

        #pragma unroll
        for (int i = 0; i < 2; i++) {
            #pragma unroll
            for (int h = 0; h < 2; h++) {
                int m = bm * 128 + wm * 32 + i * 16 + (lane >> 2) + h * 8;
                size_t orow = (size_t)m * DIM_D;
                #pragma unroll
                for (int j = 0; j < 4; j++) {
                    int n = bn * 128 + wn * 32 + j * 8 + (lane & 3) * 2;
                    float2 o0 = make_float2(c0[i][j][h * 2 + 0] * 16.0f,
                                            c0[i][j][h * 2 + 1] * 16.0f);
                    float2 o1 = make_float2(c1[i][j][h * 2 + 0] * 16.0f,
                                            c1[i][j][h * 2 + 1] * 16.0f);
                    *reinterpret_cast<float2*>(out + orow + n) = o0;
                    *reinterpret_cast<float2*>(out + orow + n + 64) = o1;
                }
            }
        }
    }
}

// ---------------- launch ------------------------------------------------------
extern "C" void kernel_launch(void* const* d_in, const int* in_sizes, int n_in,
                              void* d_out, int out_size) {
    const float* x  = (const float*)d_in[0];
    const float* Wg = (const float*)d_in[1];
    const float* Wu = (const float*)d_in[2];
    const float* Wd = (const float*)d_in[3];
    float* out = (float*)d_out;

    int nsm = 148;
    cudaDeviceGetAttribute(&nsm, cudaDevAttrMultiProcessorCount, 0);
    int ncta = 2 * nsm;

    cudaFuncSetAttribute(gemm1_bf, cudaFuncAttributeMaxDynamicSharedMemorySize, G1_SMEM);
    cudaFuncSetAttribute(gemm3_f16, cudaFuncAttributeMaxDynamicSharedMemorySize, G3_SMEM);

    quant_kernel<<<DIM_M, 256>>>(x);

    const int n4 = DIM_H * DIM_D / 4;  // 4194304
    sign_fused_kernel<<<3 * n4 / 256, 256>>>((const float4*)Wg, (const float4*)Wu,
                                             (const float4*)Wd, n4);

    gemm1_bf<<<ncta, 256, G1_SMEM>>>();

    gemm3_f16<<<ncta, 256, G3_SMEM>>>(out);
}

// round 13
// speedup vs baseline: 1.1574x; 1.0973x over previous
#include <cuda_runtime.h>
#include <cuda_bf16.h>
#include <cuda_fp16.h>
#include <cstdint>

#define DIM_M 8192   // B*S
#define DIM_D 2048
#define DIM_H 8192

// ---------------- scratch (static device globals; no allocation) -------------
__device__ __nv_bfloat16 g_xq[(size_t)DIM_M * DIM_D];     // integer-valued quantized activations (bf16)
__device__ float         g_scale[DIM_M];                  // amax/127 per row
__device__ __nv_bfloat16 g_wg[(size_t)DIM_H * DIM_D];     // sign(W_g) bf16
__device__ __nv_bfloat16 g_wu[(size_t)DIM_H * DIM_D];     // sign(W_u) bf16
__device__ __half        g_wd[(size_t)DIM_D * DIM_H];     // sign(W_d) fp16
__device__ __half        g_p[(size_t)DIM_M * DIM_H];      // p * 2^-4, fp16
__device__ int           g_t1;                            // gemm1 tile queue head
__device__ int           g_t3;                            // gemm3 tile queue head

// ---------------- PTX helpers -------------------------------------------------
__device__ __forceinline__ uint32_t smem_u32(const void* p) {
    uint32_t a;
    asm("{ .reg .u64 t; cvta.to.shared.u64 t, %1; cvt.u32.u64 %0, t; }" : "=r"(a) : "l"(p));
    return a;
}
__device__ __forceinline__ void cp_async16(uint32_t smem, const void* gmem) {
    asm volatile("cp.async.cg.shared.global [%0], [%1], 16;\n" :: "r"(smem), "l"(gmem));
}
__device__ __forceinline__ void ldm4(uint32_t* r, uint32_t addr) {
    asm volatile("ldmatrix.sync.aligned.m8n8.x4.shared.b16 {%0,%1,%2,%3}, [%4];"
                 : "=r"(r[0]), "=r"(r[1]), "=r"(r[2]), "=r"(r[3]) : "r"(addr));
}
__device__ __forceinline__ void mma_bf16(float* d, const uint32_t* a, uint32_t b0, uint32_t b1) {
    asm volatile(
        "mma.sync.aligned.m16n8k16.row.col.f32.bf16.bf16.f32 "
        "{%0,%1,%2,%3}, {%4,%5,%6,%7}, {%8,%9}, {%0,%1,%2,%3};\n"
        : "+f"(d[0]), "+f"(d[1]), "+f"(d[2]), "+f"(d[3])
        : "r"(a[0]), "r"(a[1]), "r"(a[2]), "r"(a[3]), "r"(b0), "r"(b1));
}
__device__ __forceinline__ void mma_f16(float* d, const uint32_t* a, uint32_t b0, uint32_t b1) {
    asm volatile(
        "mma.sync.aligned.m16n8k16.row.col.f32.f16.f16.f32 "
        "{%0,%1,%2,%3}, {%4,%5,%6,%7}, {%8,%9}, {%0,%1,%2,%3};\n"
        : "+f"(d[0]), "+f"(d[1]), "+f"(d[2]), "+f"(d[3])
        : "r"(a[0]), "r"(a[1]), "r"(a[2]), "r"(a[3]), "r"(b0), "r"(b1));
}

// ---- mbarrier primitives (standard PTX, sm_80/sm_90 class; NOT sm_103a-gated)
__device__ __forceinline__ void mbar_init(uint32_t a, uint32_t cnt) {
    asm volatile("mbarrier.init.shared.b64 [%0], %1;" :: "r"(a), "r"(cnt) : "memory");
}
__device__ __forceinline__ void mbar_arrive(uint32_t a) {
    uint64_t st;
    asm volatile("mbarrier.arrive.shared.b64 %0, [%1];" : "=l"(st) : "r"(a) : "memory");
}
__device__ __forceinline__ void cp_mbar_arrive(uint32_t a) {
    asm volatile("cp.async.mbarrier.arrive.noinc.shared::cta.b64 [%0];" :: "r"(a) : "memory");
}
__device__ __forceinline__ void mbar_wait(uint32_t a, uint32_t ph) {
    asm volatile(
        "{\n\t.reg .pred P;\n"
        "W%=:\n\t"
        "mbarrier.try_wait.parity.acquire.cta.shared::cta.b64 P, [%0], %1, 0x989680;\n\t"
        "@P bra D%=;\n\t"
        "bra W%=;\n"
        "D%=:\n\t}"
        :: "r"(a), "r"(ph) : "memory");
}

// ---------------- misc math ---------------------------------------------------
__device__ __forceinline__ float siluf(float x) { return x / (1.0f + expf(-x)); }

__device__ __forceinline__ float block_reduce(float v, float* sm, bool ismax) {
    int lane = threadIdx.x & 31, wid = threadIdx.x >> 5;
    #pragma unroll
    for (int o = 16; o; o >>= 1) {
        float t = __shfl_xor_sync(0xffffffffu, v, o);
        v = ismax ? fmaxf(v, t) : v + t;
    }
    if (lane == 0) sm[wid] = v;
    __syncthreads();
    float out = sm[0];
    #pragma unroll
    for (int i = 1; i < 8; i++) out = ismax ? fmaxf(out, sm[i]) : out + sm[i];
    __syncthreads();
    return out;
}

// ---------------- kernel 1: layernorm + activation quant (bf16 ints) ----------
__global__ __launch_bounds__(256) void quant_kernel(const float* __restrict__ x) {
    const int row = blockIdx.x, tid = threadIdx.x;
    if (row == 0 && tid == 0) { g_t1 = 0; g_t3 = 0; }   // reset tile queues per launch
    const float4* xr = reinterpret_cast<const float4*>(x + (size_t)row * DIM_D);
    float4 a = xr[2 * tid], b = xr[2 * tid + 1];
    float v[8] = {a.x, a.y, a.z, a.w, b.x, b.y, b.z, b.w};

    __shared__ float sred[8];

    float s = 0.f;
    #pragma unroll
    for (int i = 0; i < 8; i++) s += v[i];
    s = block_reduce(s, sred, false);
    float mean = s * (1.0f / DIM_D);

    float q = 0.f;
    #pragma unroll
    for (int i = 0; i < 8; i++) { float d = v[i] - mean; q += d * d; }
    q = block_reduce(q, sred, false);
    float rstd = rsqrtf(q * (1.0f / DIM_D) + 1e-8f);

    float amax = 0.f;
    #pragma unroll
    for (int i = 0; i < 8; i++) amax = fmaxf(amax, fabsf((v[i] - mean) * rstd));
    amax = block_reduce(amax, sred, true);

    float sq = (amax > 0.f) ? (127.0f / amax) : 0.0f;

    uint32_t packed[4];
    #pragma unroll
    for (int i = 0; i < 4; i++) {
        float t0 = rintf((v[2 * i] - mean) * rstd * sq);
        float t1 = rintf((v[2 * i + 1] - mean) * rstd * sq);
        t0 = fminf(fmaxf(t0, -128.f), 127.f);
        t1 = fminf(fmaxf(t1, -128.f), 127.f);
        uint32_t lo = (uint32_t)__bfloat16_as_ushort(__float2bfloat16(t0));
        uint32_t hi = (uint32_t)__bfloat16_as_ushort(__float2bfloat16(t1));
        packed[i] = lo | (hi << 16);
    }
    reinterpret_cast<uint4*>(g_xq + (size_t)row * DIM_D)[tid] =
        make_uint4(packed[0], packed[1], packed[2], packed[3]);

    if (tid == 0) g_scale[row] = amax * (1.0f / 127.0f);
}

// ---------------- kernel 2: fused sign conversion (Wg,Wu -> bf16; Wd -> fp16) --
__global__ __launch_bounds__(256) void sign_fused_kernel(
        const float4* __restrict__ wg, const float4* __restrict__ wu,
        const float4* __restrict__ wd, int n4) {
    int gi = blockIdx.x * 256 + threadIdx.x;
    int which = gi / n4;          // 0: Wg, 1: Wu, 2: Wd
    int i = gi - which * n4;
    if (which < 2) {
        const float4 v = (which == 0) ? wg[i] : wu[i];
        __nv_bfloat16* o = (which == 0) ? g_wg : g_wu;
        float f0 = (v.x > 0.f) ? 1.f : ((v.x < 0.f) ? -1.f : 0.f);
        float f1 = (v.y > 0.f) ? 1.f : ((v.y < 0.f) ? -1.f : 0.f);
        float f2 = (v.z > 0.f) ? 1.f : ((v.z < 0.f) ? -1.f : 0.f);
        float f3 = (v.w > 0.f) ? 1.f : ((v.w < 0.f) ? -1.f : 0.f);
        uint32_t a0 = (uint32_t)__bfloat16_as_ushort(__float2bfloat16(f0));
        uint32_t a1 = (uint32_t)__bfloat16_as_ushort(__float2bfloat16(f1));
        uint32_t a2 = (uint32_t)__bfloat16_as_ushort(__float2bfloat16(f2));
        uint32_t a3 = (uint32_t)__bfloat16_as_ushort(__float2bfloat16(f3));
        uint2 out;
        out.x = a0 | (a1 << 16);
        out.y = a2 | (a3 << 16);
        reinterpret_cast<uint2*>(o)[i] = out;
    } else {
        const float4 v = wd[i];
        float f0 = (v.x > 0.f) ? 1.f : ((v.x < 0.f) ? -1.f : 0.f);
        float f1 = (v.y > 0.f) ? 1.f : ((v.y < 0.f) ? -1.f : 0.f);
        float f2 = (v.z > 0.f) ? 1.f : ((v.z < 0.f) ? -1.f : 0.f);
        float f3 = (v.w > 0.f) ? 1.f : ((v.w < 0.f) ? -1.f : 0.f);
        __half2 h0 = __floats2half2_rn(f0, f1);
        __half2 h1 = __floats2half2_rn(f2, f3);
        uint2 out;
        out.x = *reinterpret_cast<uint32_t*>(&h0);
        out.y = *reinterpret_cast<uint32_t*>(&h1);
        reinterpret_cast<uint2*>(g_wd)[i] = out;
    }
}

extern __shared__ __align__(128) char dsm[];

// =============================================================================
// Pipelined-mbarrier GEMMs: 3 stages, per-stage full/empty mbarriers (count 256),
// no CTA-wide barrier in the steady loop -> warps drift up to 2 chunks.
// Stage layout identical to R12 (144B rows): [A | B0 | B1] = 36864 B/stage.
// Barriers at offset 3*STAGE: full[3] @+0, empty[3] @+24, tile slot @+48.
// =============================================================================
#define STAGE  36864
#define NSTG   3
#define BAR_OFF (NSTG * STAGE)
#define SMEM_TOT (BAR_OFF + 64)

#define G1_TILES (128 * 64)
#define G1_NCHUNK (DIM_D / 64)   // 32
#define G3_TILES (16 * 64)
#define G3_NCHUNK (DIM_H / 64)   // 128

__global__ __launch_bounds__(256, 2) void gemm1_bf() {
    const int tid = threadIdx.x, warp = tid >> 5, lane = tid & 31;
    const int wm = warp & 3, wn = warp >> 2;
    uint32_t sb = smem_u32(dsm);
    const uint32_t fullb = sb + BAR_OFF, emptyb = sb + BAR_OFF + 24;
    int* s_t = reinterpret_cast<int*>(dsm + BAR_OFF + 48);

    const uint32_t lrow = (lane & 15), lseg = (lane >> 4) << 4;

    while (true) {
        if (tid == 0) {
            *s_t = atomicAdd(&g_t1, 1);
            #pragma unroll
            for (int s = 0; s < NSTG; s++) {
                mbar_init(fullb + s * 8, 256);
                mbar_init(emptyb + s * 8, 256);
            }
        }
        __syncthreads();
        int t = *s_t;
        if (t >= G1_TILES) break;
        int bm = t >> 7, bn = t & 127;

        const __nv_bfloat16* Ag = g_xq + (size_t)bm * 128 * DIM_D;
        const __nv_bfloat16* Bg = g_wg + (size_t)bn * 64 * DIM_D;
        const __nv_bfloat16* Bu = g_wu + (size_t)bn * 64 * DIM_D;

        float cg[2][4][4], cu[2][4][4];
        #pragma unroll
        for (int i = 0; i < 2; i++)
            #pragma unroll
            for (int j = 0; j < 4; j++)
                #pragma unroll
                for (int e = 0; e < 4; e++) { cg[i][j][e] = 0.f; cu[i][j][e] = 0.f; }

        auto load = [&](int st, int kt) {
            int k0 = kt * 64;
            uint32_t base = sb + st * STAGE;
            #pragma unroll
            for (int it = 0; it < 4; it++) {
                int ch = tid + it * 256;
                int row = ch >> 3, seg = ch & 7;
                cp_async16(base + row * 144 + seg * 16,
                           Ag + (size_t)row * DIM_D + k0 + seg * 8);
            }
            #pragma unroll
            for (int it = 0; it < 2; it++) {
                int ch = tid + it * 256;
                int row = ch >> 3, seg = ch & 7;
                uint32_t d = row * 144 + seg * 16;
                size_t gofs = (size_t)row * DIM_D + k0 + seg * 8;
                cp_async16(base + 18432 + d, Bg + gofs);
                cp_async16(base + 27648 + d, Bu + gofs);
            }
            cp_mbar_arrive(fullb + st * 8);
        };

        // prologue: chunks 0 and 1
        load(0, 0);
        load(1, 1);
        int sc = 0, pc = 0;   // consume cursor
        int sl = 2, pl = 0;   // load cursor (chunk i+2)

        for (int i = 0; i < G1_NCHUNK; i++) {
            int j = i + 2;
            if (j < G1_NCHUNK) {
                if (j >= NSTG) mbar_wait(emptyb + sl * 8, pl ^ 1);
                load(sl, j);
                if (++sl == NSTG) { sl = 0; pl ^= 1; }
            }
            mbar_wait(fullb + sc * 8, pc);
            uint32_t base = sb + sc * STAGE;
            #pragma unroll
            for (int kk = 0; kk < 4; kk++) {
                uint32_t koff = kk * 32 + lseg;
                uint32_t a[2][4], bg[2][4], bu[2][4];
                #pragma unroll
                for (int i2 = 0; i2 < 2; i2++)
                    ldm4(a[i2], base + (wm * 32 + i2 * 16 + lrow) * 144 + koff);
                #pragma unroll
                for (int j2 = 0; j2 < 2; j2++) {
                    uint32_t rb = (wn * 32 + j2 * 16 + lrow) * 144 + koff;
                    ldm4(bg[j2], base + 18432 + rb);
                    ldm4(bu[j2], base + 27648 + rb);
                }
                #pragma unroll
                for (int j3 = 0; j3 < 4; j3++) {
                    int j2 = j3 >> 1, hh = j3 & 1;
                    #pragma unroll
                    for (int i2 = 0; i2 < 2; i2++) {
                        mma_bf16(cg[i2][j3], a[i2], bg[j2][hh], bg[j2][2 + hh]);
                        mma_bf16(cu[i2][j3], a[i2], bu[j2][hh], bu[j2][2 + hh]);
                    }
                }
            }
            mbar_arrive(emptyb + sc * 8);
            if (++sc == NSTG) { sc = 0; pc ^= 1; }
        }

        // epilogue: scale, silu, product, *2^-4, fp16 store
        #pragma unroll
        for (int i = 0; i < 2; i++) {
            #pragma unroll
            for (int h = 0; h < 2; h++) {
                int m = bm * 128 + wm * 32 + i * 16 + (lane >> 2) + h * 8;
                float s = g_scale[m];
                size_t orow = (size_t)m * DIM_H;
                #pragma unroll
                for (int j = 0; j < 4; j++) {
                    int n = bn * 64 + wn * 32 + j * 8 + (lane & 3) * 2;
                    float g0 = cg[i][j][h * 2 + 0] * s;
                    float g1 = cg[i][j][h * 2 + 1] * s;
                    float u0 = cu[i][j][h * 2 + 0] * s;
                    float u1 = cu[i][j][h * 2 + 1] * s;
                    float p0 = siluf(g0) * u0 * 0.0625f;
                    float p1 = siluf(g1) * u1 * 0.0625f;
                    __half2 hp = __floats2half2_rn(p0, p1);
                    *reinterpret_cast<uint32_t*>(g_p + orow + n) =
                        *reinterpret_cast<uint32_t*>(&hp);
                }
            }
        }
        __syncthreads();   // all arrives done before barrier re-init next tile
    }
}

__global__ __launch_bounds__(256, 2) void gemm3_f16(float* __restrict__ out) {
    const int tid = threadIdx.x, warp = tid >> 5, lane = tid & 31;
    const int wm = warp & 3, wn = warp >> 2;
    uint32_t sb = smem_u32(dsm);
    const uint32_t fullb = sb + BAR_OFF, emptyb = sb + BAR_OFF + 24;
    int* s_t = reinterpret_cast<int*>(dsm + BAR_OFF + 48);

    const uint32_t lrow = (lane & 15), lseg = (lane >> 4) << 4;

    while (true) {
        if (tid == 0) {
            *s_t = atomicAdd(&g_t3, 1);
            #pragma unroll
            for (int s = 0; s < NSTG; s++) {
                mbar_init(fullb + s * 8, 256);
                mbar_init(emptyb + s * 8, 256);
            }
        }
        __syncthreads();
        int t = *s_t;
        if (t >= G3_TILES) break;
        int bm = t >> 4, bn = t & 15;

        const __half* Ap = g_p  + (size_t)bm * 128 * DIM_H;
        const __half* B0 = g_wd + (size_t)bn * 128 * DIM_H;
        const __half* B1 = B0 + (size_t)64 * DIM_H;

        float c0[2][4][4], c1[2][4][4];
        #pragma unroll
        for (int i = 0; i < 2; i++)
            #pragma unroll
            for (int j = 0; j < 4; j++)
                #pragma unroll
                for (int e = 0; e < 4; e++) { c0[i][j][e] = 0.f; c1[i][j][e] = 0.f; }

        auto load = [&](int st, int kt) {
            int k0 = kt * 64;
            uint32_t base = sb + st * STAGE;
            #pragma unroll
            for (int it = 0; it < 4; it++) {
                int ch = tid + it * 256;
                int row = ch >> 3, seg = ch & 7;
                cp_async16(base + row * 144 + seg * 16,
                           Ap + (size_t)row * DIM_H + k0 + seg * 8);
            }
            #pragma unroll
            for (int it = 0; it < 2; it++) {
                int ch = tid + it * 256;
                int row = ch >> 3, seg = ch & 7;
                uint32_t d = row * 144 + seg * 16;
                size_t gofs = (size_t)row * DIM_H + k0 + seg * 8;
                cp_async16(base + 18432 + d, B0 + gofs);
                cp_async16(base + 27648 + d, B1 + gofs);
            }
            cp_mbar_arrive(fullb + st * 8);
        };

        load(0, 0);
        load(1, 1);
        int sc = 0, pc = 0;
        int sl = 2, pl = 0;

        for (int i = 0; i < G3_NCHUNK; i++) {
            int j = i + 2;
            if (j < G3_NCHUNK) {
                if (j >= NSTG) mbar_wait(emptyb + sl * 8, pl ^ 1);
                load(sl, j);
                if (++sl == NSTG) { sl = 0; pl ^= 1; }
            }
            mbar_wait(fullb + sc * 8, pc);
            uint32_t base = sb + sc * STAGE;
            #pragma unroll
            for (int kk = 0; kk < 4; kk++) {
                uint32_t koff = kk * 32 + lseg;
                uint32_t a[2][4], b0[2][4], b1[2][4];
                #pragma unroll
                for (int i2 = 0; i2 < 2; i2++)
                    ldm4(a[i2], base + (wm * 32 + i2 * 16 + lrow) * 144 + koff);
                #pragma unroll
                for (int j2 = 0; j2 < 2; j2++) {
                    uint32_t rb = (wn * 32 + j2 * 16 + lrow) * 144 + koff;
                    ldm4(b0[j2], base + 18432 + rb);
                    ldm4(b1[j2], base + 27648 + rb);
                }
                #pragma unroll
                for (int j3 = 0; j3 < 4; j3++) {
                    int j2 = j3 >> 1, hh = j3 & 1;
                    #pragma unroll
                    for (int i2 = 0; i2 < 2; i2++) {
                        mma_f16(c0[i2][j3], a[i2], b0[j2][hh], b0[j2][2 + hh]);
                        mma_f16(c1[i2][j3], a[i2], b1[j2][hh], b1[j2][2 + hh]);
                    }
                }
            }
            mbar_arrive(emptyb + sc * 8);
            if (++sc == NSTG) { sc = 0; pc ^= 1; }
        }

        #pragma unroll
        for (int i = 0; i < 2; i++) {
            #pragma unroll
            for (int h = 0; h < 2; h++) {
                int m = bm * 128 + wm * 32 + i * 16 + (lane >> 2) + h * 8;
                size_t orow = (size_t)m * DIM_D;
                #pragma unroll
                for (int j = 0; j < 4; j++) {
                    int n = bn * 128 + wn * 32 + j * 8 + (lane & 3) * 2;
                    float2 o0 = make_float2(c0[i][j][h * 2 + 0] * 16.0f,
                                            c0[i][j][h * 2 + 1] * 16.0f);
                    float2 o1 = make_float2(c1[i][j][h * 2 + 0] * 16.0f,
                                            c1[i][j][h * 2 + 1] * 16.0f);
                    *reinterpret_cast<float2*>(out + orow + n) = o0;
                    *reinterpret_cast<float2*>(out + orow + n + 64) = o1;
                }
            }
        }
        __syncthreads();
    }
}

// ---------------- launch ------------------------------------------------------
extern "C" void kernel_launch(void* const* d_in, const int* in_sizes, int n_in,
                              void* d_out, int out_size) {
    const float* x  = (const float*)d_in[0];
    const float* Wg = (const float*)d_in[1];
    const float* Wu = (const float*)d_in[2];
    const float* Wd = (const float*)d_in[3];
    float* out = (float*)d_out;

    int nsm = 148;
    cudaDeviceGetAttribute(&nsm, cudaDevAttrMultiProcessorCount, 0);
    int ncta = 2 * nsm;

    cudaFuncSetAttribute(gemm1_bf, cudaFuncAttributeMaxDynamicSharedMemorySize, SMEM_TOT);
    cudaFuncSetAttribute(gemm3_f16, cudaFuncAttributeMaxDynamicSharedMemorySize, SMEM_TOT);

    quant_kernel<<<DIM_M, 256>>>(x);

    const int n4 = DIM_H * DIM_D / 4;  // 4194304
    sign_fused_kernel<<<3 * n4 / 256, 256>>>((const float4*)Wg, (const float4*)Wu,
                                             (const float4*)Wd, n4);

    gemm1_bf<<<ncta, 256, SMEM_TOT>>>();

    gemm3_f16<<<ncta, 256, SMEM_TOT>>>(out);
}

// round 17
// speedup vs baseline: 1.2975x; 1.1210x over previous
#include <cuda_runtime.h>
#include <cuda_bf16.h>
#include <cuda_fp16.h>
#include <cstdint>

#define DIM_M 8192   // B*S
#define DIM_D 2048
#define DIM_H 8192

// ---------------- scratch (static device globals; no allocation) -------------
__device__ __nv_bfloat16 g_xq[(size_t)DIM_M * DIM_D];     // integer-valued quantized activations (bf16)
__device__ float         g_scale[DIM_M];                  // amax/127 per row
__device__ __nv_bfloat16 g_wg[(size_t)DIM_H * DIM_D];     // sign(W_g) bf16
__device__ __nv_bfloat16 g_wu[(size_t)DIM_H * DIM_D];     // sign(W_u) bf16
__device__ __half        g_wd[(size_t)DIM_D * DIM_H];     // sign(W_d) fp16
__device__ __half        g_p[(size_t)DIM_M * DIM_H];      // p * 2^-4, fp16
__device__ int           g_t1;                            // gemm1 tile queue head
__device__ int           g_t3;                            // gemm3 tile queue head

// ---------------- PTX helpers -------------------------------------------------
__device__ __forceinline__ uint32_t smem_u32(const void* p) {
    uint32_t a;
    asm("{ .reg .u64 t; cvta.to.shared.u64 t, %1; cvt.u32.u64 %0, t; }" : "=r"(a) : "l"(p));
    return a;
}
__device__ __forceinline__ void cp_async16(uint32_t smem, const void* gmem) {
    asm volatile("cp.async.cg.shared.global [%0], [%1], 16;\n" :: "r"(smem), "l"(gmem));
}
__device__ __forceinline__ void ldm4(uint32_t* r, uint32_t addr) {
    asm volatile("ldmatrix.sync.aligned.m8n8.x4.shared.b16 {%0,%1,%2,%3}, [%4];"
                 : "=r"(r[0]), "=r"(r[1]), "=r"(r[2]), "=r"(r[3]) : "r"(addr));
}
__device__ __forceinline__ void mma_bf16(float* d, const uint32_t* a, uint32_t b0, uint32_t b1) {
    asm volatile(
        "mma.sync.aligned.m16n8k16.row.col.f32.bf16.bf16.f32 "
        "{%0,%1,%2,%3}, {%4,%5,%6,%7}, {%8,%9}, {%0,%1,%2,%3};\n"
        : "+f"(d[0]), "+f"(d[1]), "+f"(d[2]), "+f"(d[3])
        : "r"(a[0]), "r"(a[1]), "r"(a[2]), "r"(a[3]), "r"(b0), "r"(b1));
}
__device__ __forceinline__ void mma_f16(float* d, const uint32_t* a, uint32_t b0, uint32_t b1) {
    asm volatile(
        "mma.sync.aligned.m16n8k16.row.col.f32.f16.f16.f32 "
        "{%0,%1,%2,%3}, {%4,%5,%6,%7}, {%8,%9}, {%0,%1,%2,%3};\n"
        : "+f"(d[0]), "+f"(d[1]), "+f"(d[2]), "+f"(d[3])
        : "r"(a[0]), "r"(a[1]), "r"(a[2]), "r"(a[3]), "r"(b0), "r"(b1));
}

// ---- mbarrier primitives (standard PTX, sm_80/sm_90 class; NOT sm_103a-gated)
__device__ __forceinline__ void mbar_init(uint32_t a, uint32_t cnt) {
    asm volatile("mbarrier.init.shared.b64 [%0], %1;" :: "r"(a), "r"(cnt) : "memory");
}
__device__ __forceinline__ void cp_mbar_arrive(uint32_t a) {
    asm volatile("cp.async.mbarrier.arrive.noinc.shared::cta.b64 [%0];" :: "r"(a) : "memory");
}
__device__ __forceinline__ void mbar_wait(uint32_t a, uint32_t ph) {
    asm volatile(
        "{\n\t.reg .pred P;\n"
        "W%=:\n\t"
        "mbarrier.try_wait.parity.acquire.cta.shared::cta.b64 P, [%0], %1, 0x989680;\n\t"
        "@P bra D%=;\n\t"
        "bra W%=;\n"
        "D%=:\n\t}"
        :: "r"(a), "r"(ph) : "memory");
}

// SW128 swizzle on byte offsets (bits[6:4] ^= bits[9:7]); conflict-free 16B lanes
__device__ __forceinline__ uint32_t sw128(uint32_t off) {
    return off ^ ((off >> 3) & 0x70);
}

// ---------------- misc math ---------------------------------------------------
__device__ __forceinline__ float siluf(float x) { return x / (1.0f + expf(-x)); }

__device__ __forceinline__ float block_reduce(float v, float* sm, bool ismax) {
    int lane = threadIdx.x & 31, wid = threadIdx.x >> 5;
    #pragma unroll
    for (int o = 16; o; o >>= 1) {
        float t = __shfl_xor_sync(0xffffffffu, v, o);
        v = ismax ? fmaxf(v, t) : v + t;
    }
    if (lane == 0) sm[wid] = v;
    __syncthreads();
    float out = sm[0];
    #pragma unroll
    for (int i = 1; i < 8; i++) out = ismax ? fmaxf(out, sm[i]) : out + sm[i];
    __syncthreads();
    return out;
}

// ---------------- kernel 1: layernorm + activation quant (bf16 ints) ----------
__global__ __launch_bounds__(256) void quant_kernel(const float* __restrict__ x) {
    const int row = blockIdx.x, tid = threadIdx.x;
    if (row == 0 && tid == 0) { g_t1 = 0; g_t3 = 0; }   // reset tile queues per launch
    const float4* xr = reinterpret_cast<const float4*>(x + (size_t)row * DIM_D);
    float4 a = xr[2 * tid], b = xr[2 * tid + 1];
    float v[8] = {a.x, a.y, a.z, a.w, b.x, b.y, b.z, b.w};

    __shared__ float sred[8];

    float s = 0.f;
    #pragma unroll
    for (int i = 0; i < 8; i++) s += v[i];
    s = block_reduce(s, sred, false);
    float mean = s * (1.0f / DIM_D);

    float q = 0.f;
    #pragma unroll
    for (int i = 0; i < 8; i++) { float d = v[i] - mean; q += d * d; }
    q = block_reduce(q, sred, false);
    float rstd = rsqrtf(q * (1.0f / DIM_D) + 1e-8f);

    float amax = 0.f;
    #pragma unroll
    for (int i = 0; i < 8; i++) amax = fmaxf(amax, fabsf((v[i] - mean) * rstd));
    amax = block_reduce(amax, sred, true);

    float sq = (amax > 0.f) ? (127.0f / amax) : 0.0f;

    uint32_t packed[4];
    #pragma unroll
    for (int i = 0; i < 4; i++) {
        float t0 = rintf((v[2 * i] - mean) * rstd * sq);
        float t1 = rintf((v[2 * i + 1] - mean) * rstd * sq);
        t0 = fminf(fmaxf(t0, -128.f), 127.f);
        t1 = fminf(fmaxf(t1, -128.f), 127.f);
        uint32_t lo = (uint32_t)__bfloat16_as_ushort(__float2bfloat16(t0));
        uint32_t hi = (uint32_t)__bfloat16_as_ushort(__float2bfloat16(t1));
        packed[i] = lo | (hi << 16);
    }
    reinterpret_cast<uint4*>(g_xq + (size_t)row * DIM_D)[tid] =
        make_uint4(packed[0], packed[1], packed[2], packed[3]);

    if (tid == 0) g_scale[row] = amax * (1.0f / 127.0f);
}

// ---------------- kernel 2: fused sign conversion (Wg,Wu -> bf16; Wd -> fp16) --
__global__ __launch_bounds__(256) void sign_fused_kernel(
        const float4* __restrict__ wg, const float4* __restrict__ wu,
        const float4* __restrict__ wd, int n4) {
    int gi = blockIdx.x * 256 + threadIdx.x;
    int which = gi / n4;          // 0: Wg, 1: Wu, 2: Wd
    int i = gi - which * n4;
    if (which < 2) {
        const float4 v = (which == 0) ? wg[i] : wu[i];
        __nv_bfloat16* o = (which == 0) ? g_wg : g_wu;
        float f0 = (v.x > 0.f) ? 1.f : ((v.x < 0.f) ? -1.f : 0.f);
        float f1 = (v.y > 0.f) ? 1.f : ((v.y < 0.f) ? -1.f : 0.f);
        float f2 = (v.z > 0.f) ? 1.f : ((v.z < 0.f) ? -1.f : 0.f);
        float f3 = (v.w > 0.f) ? 1.f : ((v.w < 0.f) ? -1.f : 0.f);
        uint32_t a0 = (uint32_t)__bfloat16_as_ushort(__float2bfloat16(f0));
        uint32_t a1 = (uint32_t)__bfloat16_as_ushort(__float2bfloat16(f1));
        uint32_t a2 = (uint32_t)__bfloat16_as_ushort(__float2bfloat16(f2));
        uint32_t a3 = (uint32_t)__bfloat16_as_ushort(__float2bfloat16(f3));
        uint2 out;
        out.x = a0 | (a1 << 16);
        out.y = a2 | (a3 << 16);
        reinterpret_cast<uint2*>(o)[i] = out;
    } else {
        const float4 v = wd[i];
        float f0 = (v.x > 0.f) ? 1.f : ((v.x < 0.f) ? -1.f : 0.f);
        float f1 = (v.y > 0.f) ? 1.f : ((v.y < 0.f) ? -1.f : 0.f);
        float f2 = (v.z > 0.f) ? 1.f : ((v.z < 0.f) ? -1.f : 0.f);
        float f3 = (v.w > 0.f) ? 1.f : ((v.w < 0.f) ? -1.f : 0.f);
        __half2 h0 = __floats2half2_rn(f0, f1);
        __half2 h1 = __floats2half2_rn(f2, f3);
        uint2 out;
        out.x = *reinterpret_cast<uint32_t*>(&h0);
        out.y = *reinterpret_cast<uint32_t*>(&h1);
        reinterpret_cast<uint2*>(g_wd)[i] = out;
    }
}

extern __shared__ __align__(1024) char dsm[];

// =============================================================================
// Single-barrier pipelined GEMMs: 3 stages, ONLY a full mbarrier per stage
// (count 256, cp.async noinc arrives). Protocol per chunk i:
//     wait full[i%3]  ->  load(i+1) into (i+1)%3  ->  consume i
// Safety: passing full[i] proves all threads issued chunk-i loads (top of their
// iter i-1), hence completed iter i-2 INCLUDING reads of chunk i-2 — the stage
// load(i+1) overwrites. No empty barrier, no syncthreads in the chunk loop.
// Stage layout (SW128-swizzled 128B rows): A[128] @0, B0[64] @16384, B1[64] @24576.
// =============================================================================
#define STAGE  32768u
#define NSTG   3
#define BAR_OFF (NSTG * STAGE)
#define SMEM_TOT (BAR_OFF + 64)

#define G1_TILES (128 * 64)
#define G1_NCHUNK (DIM_D / 64)   // 32
#define G3_TILES (16 * 64)
#define G3_NCHUNK (DIM_H / 64)   // 128

__global__ __launch_bounds__(256, 2) void gemm1_bf() {
    const int tid = threadIdx.x, warp = tid >> 5, lane = tid & 31;
    const int wm = warp & 3, wn = warp >> 2;
    uint32_t sb = smem_u32(dsm);
    const uint32_t fullb = sb + BAR_OFF;
    int* s_t = reinterpret_cast<int*>(dsm + BAR_OFF + 32);

    const uint32_t lrow = (lane & 15), lseg = (lane >> 4) << 4;

    while (true) {
        if (tid == 0) {
            *s_t = atomicAdd(&g_t1, 1);
            #pragma unroll
            for (int s = 0; s < NSTG; s++) mbar_init(fullb + s * 8, 256);
        }
        __syncthreads();
        int t = *s_t;
        if (t >= G1_TILES) break;
        int bm = t >> 7, bn = t & 127;

        const __nv_bfloat16* Ag = g_xq + (size_t)bm * 128 * DIM_D;
        const __nv_bfloat16* Bg = g_wg + (size_t)bn * 64 * DIM_D;
        const __nv_bfloat16* Bu = g_wu + (size_t)bn * 64 * DIM_D;

        float cg[2][4][4], cu[2][4][4];
        #pragma unroll
        for (int i = 0; i < 2; i++)
            #pragma unroll
            for (int j = 0; j < 4; j++)
                #pragma unroll
                for (int e = 0; e < 4; e++) { cg[i][j][e] = 0.f; cu[i][j][e] = 0.f; }

        auto load = [&](int st, int kt) {
            int k0 = kt * 64;
            uint32_t base = sb + st * STAGE;
            #pragma unroll
            for (int it = 0; it < 4; it++) {
                int ch = tid + it * 256;
                int row = ch >> 3, seg = ch & 7;
                uint32_t off = (uint32_t)(row * 128 + seg * 16);
                cp_async16(base + sw128(off),
                           Ag + (size_t)row * DIM_D + k0 + seg * 8);
            }
            #pragma unroll
            for (int it = 0; it < 2; it++) {
                int ch = tid + it * 256;
                int row = ch >> 3, seg = ch & 7;
                uint32_t swo = sw128((uint32_t)(row * 128 + seg * 16));
                size_t gofs = (size_t)row * DIM_D + k0 + seg * 8;
                cp_async16(base + 16384 + swo, Bg + gofs);
                cp_async16(base + 24576 + swo, Bu + gofs);
            }
            cp_mbar_arrive(fullb + st * 8);
        };

        load(0, 0);
        int ph = 0;

        for (int i = 0; i < G1_NCHUNK; i++) {
            int sc = i % 3;
            mbar_wait(fullb + sc * 8, ph);
            if (sc == 2) ph ^= 1;
            if (i + 1 < G1_NCHUNK) load((i + 1) % 3, i + 1);
            uint32_t base = sb + sc * STAGE;
            #pragma unroll
            for (int kk = 0; kk < 4; kk++) {
                uint32_t koff = kk * 32 + lseg;
                uint32_t a[2][4], bg[2][4], bu[2][4];
                #pragma unroll
                for (int i2 = 0; i2 < 2; i2++) {
                    uint32_t off = (wm * 32 + i2 * 16 + lrow) * 128 + koff;
                    ldm4(a[i2], base + sw128(off));
                }
                #pragma unroll
                for (int j2 = 0; j2 < 2; j2++) {
                    uint32_t swo = sw128((wn * 32 + j2 * 16 + lrow) * 128 + koff);
                    ldm4(bg[j2], base + 16384 + swo);
                    ldm4(bu[j2], base + 24576 + swo);
                }
                #pragma unroll
                for (int j3 = 0; j3 < 4; j3++) {
                    int j2 = j3 >> 1, hh = j3 & 1;
                    #pragma unroll
                    for (int i2 = 0; i2 < 2; i2++) {
                        mma_bf16(cg[i2][j3], a[i2], bg[j2][hh], bg[j2][2 + hh]);
                        mma_bf16(cu[i2][j3], a[i2], bu[j2][hh], bu[j2][2 + hh]);
                    }
                }
            }
        }

        // epilogue: scale, silu, product, *2^-4, fp16 store
        #pragma unroll
        for (int i = 0; i < 2; i++) {
            #pragma unroll
            for (int h = 0; h < 2; h++) {
                int m = bm * 128 + wm * 32 + i * 16 + (lane >> 2) + h * 8;
                float s = g_scale[m];
                size_t orow = (size_t)m * DIM_H;
                #pragma unroll
                for (int j = 0; j < 4; j++) {
                    int n = bn * 64 + wn * 32 + j * 8 + (lane & 3) * 2;
                    float g0 = cg[i][j][h * 2 + 0] * s;
                    float g1 = cg[i][j][h * 2 + 1] * s;
                    float u0 = cu[i][j][h * 2 + 0] * s;
                    float u1 = cu[i][j][h * 2 + 1] * s;
                    float p0 = siluf(g0) * u0 * 0.0625f;
                    float p1 = siluf(g1) * u1 * 0.0625f;
                    __half2 hp = __floats2half2_rn(p0, p1);
                    *reinterpret_cast<uint32_t*>(g_p + orow + n) =
                        *reinterpret_cast<uint32_t*>(&hp);
                }
            }
        }
        __syncthreads();   // all reads done before barrier re-init next tile
    }
}

__global__ __launch_bounds__(256, 2) void gemm3_f16(float* __restrict__ out) {
    const int tid = threadIdx.x, warp = tid >> 5, lane = tid & 31;
    const int wm = warp & 3, wn = warp >> 2;
    uint32_t sb = smem_u32(dsm);
    const uint32_t fullb = sb + BAR_OFF;
    int* s_t = reinterpret_cast<int*>(dsm + BAR_OFF + 32);

    const uint32_t lrow = (lane & 15), lseg = (lane >> 4) << 4;

    while (true) {
        if (tid == 0) {
            *s_t = atomicAdd(&g_t3, 1);
            #pragma unroll
            for (int s = 0; s < NSTG; s++) mbar_init(fullb + s * 8, 256);
        }
        __syncthreads();
        int t = *s_t;
        if (t >= G3_TILES) break;
        int bm = t >> 4, bn = t & 15;

        const __half* Ap = g_p  + (size_t)bm * 128 * DIM_H;
        const __half* B0 = g_wd + (size_t)bn * 128 * DIM_H;
        const __half* B1 = B0 + (size_t)64 * DIM_H;

        float c0[2][4][4], c1[2][4][4];
        #pragma unroll
        for (int i = 0; i < 2; i++)
            #pragma unroll
            for (int j = 0; j < 4; j++)
                #pragma unroll
                for (int e = 0; e < 4; e++) { c0[i][j][e] = 0.f; c1[i][j][e] = 0.f; }

        auto load = [&](int st, int kt) {
            int k0 = kt * 64;
            uint32_t base = sb + st * STAGE;
            #pragma unroll
            for (int it = 0; it < 4; it++) {
                int ch = tid + it * 256;
                int row = ch >> 3, seg = ch & 7;
                uint32_t off = (uint32_t)(row * 128 + seg * 16);
                cp_async16(base + sw128(off),
                           Ap + (size_t)row * DIM_H + k0 + seg * 8);
            }
            #pragma unroll
            for (int it = 0; it < 2; it++) {
                int ch = tid + it * 256;
                int row = ch >> 3, seg = ch & 7;
                uint32_t swo = sw128((uint32_t)(row * 128 + seg * 16));
                size_t gofs = (size_t)row * DIM_H + k0 + seg * 8;
                cp_async16(base + 16384 + swo, B0 + gofs);
                cp_async16(base + 24576 + swo, B1 + gofs);
            }
            cp_mbar_arrive(fullb + st * 8);
        };

        load(0, 0);
        int ph = 0;

        for (int i = 0; i < G3_NCHUNK; i++) {
            int sc = i % 3;
            mbar_wait(fullb + sc * 8, ph);
            if (sc == 2) ph ^= 1;
            if (i + 1 < G3_NCHUNK) load((i + 1) % 3, i + 1);
            uint32_t base = sb + sc * STAGE;
            #pragma unroll
            for (int kk = 0; kk < 4; kk++) {
                uint32_t koff = kk * 32 + lseg;
                uint32_t a[2][4], b0[2][4], b1[2][4];
                #pragma unroll
                for (int i2 = 0; i2 < 2; i2++) {
                    uint32_t off = (wm * 32 + i2 * 16 + lrow) * 128 + koff;
                    ldm4(a[i2], base + sw128(off));
                }
                #pragma unroll
                for (int j2 = 0; j2 < 2; j2++) {
                    uint32_t swo = sw128((wn * 32 + j2 * 16 + lrow) * 128 + koff);
                    ldm4(b0[j2], base + 16384 + swo);
                    ldm4(b1[j2], base + 24576 + swo);
                }
                #pragma unroll
                for (int j3 = 0; j3 < 4; j3++) {
                    int j2 = j3 >> 1, hh = j3 & 1;
                    #pragma unroll
                    for (int i2 = 0; i2 < 2; i2++) {
                        mma_f16(c0[i2][j3], a[i2], b0[j2][hh], b0[j2][2 + hh]);
                        mma_f16(c1[i2][j3], a[i2], b1[j2][hh], b1[j2][2 + hh]);
                    }
                }
            }
        }

        #pragma unroll
        for (int i = 0; i < 2; i++) {
            #pragma unroll
            for (int h = 0; h < 2; h++) {
                int m = bm * 128 + wm * 32 + i * 16 + (lane >> 2) + h * 8;
                size_t orow = (size_t)m * DIM_D;
                #pragma unroll
                for (int j = 0; j < 4; j++) {
                    int n = bn * 128 + wn * 32 + j * 8 + (lane & 3) * 2;
                    float2 o0 = make_float2(c0[i][j][h * 2 + 0] * 16.0f,
                                            c0[i][j][h * 2 + 1] * 16.0f);
                    float2 o1 = make_float2(c1[i][j][h * 2 + 0] * 16.0f,
                                            c1[i][j][h * 2 + 1] * 16.0f);
                    *reinterpret_cast<float2*>(out + orow + n) = o0;
                    *reinterpret_cast<float2*>(out + orow + n + 64) = o1;
                }
            }
        }
        __syncthreads();
    }
}

// ---------------- launch ------------------------------------------------------
extern "C" void kernel_launch(void* const* d_in, const int* in_sizes, int n_in,
                              void* d_out, int out_size) {
    const float* x  = (const float*)d_in[0];
    const float* Wg = (const float*)d_in[1];
    const float* Wu = (const float*)d_in[2];
    const float* Wd = (const float*)d_in[3];
    float* out = (float*)d_out;

    int nsm = 148;
    cudaDeviceGetAttribute(&nsm, cudaDevAttrMultiProcessorCount, 0);
    int ncta = 2 * nsm;

    cudaFuncSetAttribute(gemm1_bf, cudaFuncAttributeMaxDynamicSharedMemorySize, SMEM_TOT);
    cudaFuncSetAttribute(gemm3_f16, cudaFuncAttributeMaxDynamicSharedMemorySize, SMEM_TOT);

    quant_kernel<<<DIM_M, 256>>>(x);

    const int n4 = DIM_H * DIM_D / 4;  // 4194304
    sign_fused_kernel<<<3 * n4 / 256, 256>>>((const float4*)Wg, (const float4*)Wu,
                                             (const float4*)Wd, n4);

    gemm1_bf<<<ncta, 256, SMEM_TOT>>>();

    gemm3_f16<<<ncta, 256, SMEM_TOT>>>(out);
}